// round 9
// baseline (speedup 1.0000x reference)
#include <cuda_runtime.h>
#include <cuda_bf16.h>
#include <cuda_fp16.h>
#include <cstdint>

#define NN 50000
#define EE 800000
#define GG 64
#define BN_EPS 1e-5f

// ---------------- scratch (static device globals; no allocation) ------------
__device__ __half g_hs[(size_t)NN * 128];   // GEMM output (UNscaled), fp16
__device__ __half g_agg[(size_t)NN * 128];  // aggregated output (pre-BN), fp16
__device__ float g_dinv[NN];
__device__ int   g_deg[NN];                 // zero-init at load; k_scan re-zeroes
__device__ int   g_rowptr[NN + 1];
__device__ int   g_cursor[NN];
__device__ int   g_col[EE];
__device__ float g_sumA[3][128], g_sqA[3][128];
// pre-converted weights: [layer][k2*128 + n], half2 packed over (k=2*k2, 2*k2+1)
__device__ unsigned g_wf[3][64 * 128];

// ---------------- init: zero stats + W fp16 pre-pack -------------------------
__global__ void k_init(const float* __restrict__ W1, const float* __restrict__ W2,
                       const float* __restrict__ W3) {
    int i = blockIdx.x * blockDim.x + threadIdx.x;
    if (i < 128) {
        #pragma unroll
        for (int l = 0; l < 3; l++) { g_sumA[l][i] = 0.f; g_sqA[l][i] = 0.f; }
    }
    // W pack: layer0 48*128, layer1/2 64*128 packed k-pair elements
    int l = -1, idx = 0;
    const float* W = nullptr;
    if (i < 6144) { l = 0; idx = i; W = W1; }
    else if (i < 6144 + 8192) { l = 1; idx = i - 6144; W = W2; }
    else if (i < 6144 + 16384) { l = 2; idx = i - 14336; W = W3; }
    if (l >= 0) {
        int k2 = idx >> 7, n = idx & 127;
        float w0 = W[(size_t)(2 * k2) * 128 + n];
        float w1 = W[(size_t)(2 * k2 + 1) * 128 + n];
        __half2 p = __floats2half2_rn(w0, w1);
        g_wf[l][idx] = *reinterpret_cast<unsigned*>(&p);
    }
}

__global__ void k_deg_count(const int* __restrict__ dst) {
    int e = blockIdx.x * blockDim.x + threadIdx.x;
    if (e < EE) atomicAdd(&g_deg[dst[e]], 1);
}

// 1024-thread scan; also computes dinv and RE-ZEROES g_deg for the next call
__global__ void k_scan() {
    __shared__ int part[1024];
    const int CH = (NN + 1023) / 1024;
    int t = threadIdx.x;
    int s = 0;
    for (int j = 0; j < CH; j++) {
        int i = t * CH + j;
        if (i < NN) s += g_deg[i];
    }
    part[t] = s;
    __syncthreads();
    int own = s;
    #pragma unroll
    for (int off = 1; off < 1024; off <<= 1) {
        int v = 0;
        if (t >= off) v = part[t - off];
        __syncthreads();
        if (t >= off) part[t] += v;
        __syncthreads();
    }
    int run = part[t] - own;
    for (int j = 0; j < CH; j++) {
        int i = t * CH + j;
        if (i < NN) {
            int d = g_deg[i];
            g_cursor[i] = run;
            run += d;
            g_rowptr[i + 1] = run;
            g_dinv[i] = rsqrtf((float)d + 1.0f);   // +1 self loop
            g_deg[i] = 0;                          // keep zero-invariant
        }
    }
    if (t == 0) g_rowptr[0] = 0;
}

__global__ void k_fill(const int* __restrict__ src, const int* __restrict__ dst) {
    int e = blockIdx.x * blockDim.x + threadIdx.x;
    if (e < EE) {
        int d = dst[e];
        int p = atomicAdd(&g_cursor[d], 1);
        g_col[p] = src[e];
    }
}

// ---------------- GEMM (fp16, m16n8k16, whole-K in smem, ONE sync) -----------
// hs[m,:] = fp16( relu(bn(A[m,:])) @ W )      (no dinv here; applied in k_agg)
// Block tile 64(M) x 128(N) x K, 256 threads (8 warps: 2M x 4N, warp 32x32).

#define MMA_FP16(C, a0, a1, a2, a3, b0, b1)                                        \
    asm volatile(                                                                  \
        "mma.sync.aligned.m16n8k16.row.col.f32.f16.f16.f32 "                       \
        "{%0,%1,%2,%3},{%4,%5,%6,%7},{%8,%9},{%0,%1,%2,%3};"                       \
        : "+f"((C)[0]), "+f"((C)[1]), "+f"((C)[2]), "+f"((C)[3])                   \
        : "r"(a0), "r"(a1), "r"(a2), "r"(a3), "r"(b0), "r"(b1))

#define SAW 72    // A stride (64 rows + 8 pad), ≡8 mod 32 → conflict-free
#define SBW 136   // B stride (128 cols + 8 pad)
#define GEMM_SMEM ((64 * SAW + 64 * SBW) * 4)

__global__ __launch_bounds__(256) void k_gemm(
    const float* __restrict__ A_in, int layer, int M, int K,
    const float* __restrict__ gsum, const float* __restrict__ gsq,
    const float* __restrict__ gamma, const float* __restrict__ beta) {
    extern __shared__ unsigned smem_u[];
    unsigned* sA = smem_u;              // [K/2][64] stride SAW
    unsigned* sB = smem_u + 64 * SAW;   // [K/2][128] stride SBW
    __shared__ float sa[128], sc[128];

    int tid = threadIdx.x, lane = tid & 31, warp = tid >> 5;
    int use_bn = (gsum != nullptr);
    if (use_bn && tid < 128) {
        float mean = gsum[tid] * (1.0f / (float)NN);
        float var = gsq[tid] * (1.0f / (float)NN) - mean * mean;
        float a = gamma[tid] * rsqrtf(var + BN_EPS);
        sa[tid] = a;
        sc[tid] = beta[tid] - mean * a;
    }
    __syncthreads();

    int row0 = blockIdx.x * 64;
    int wm = (warp >> 2) * 32;     // 2 M groups
    int wn = (warp & 3) * 32;      // 4 N groups
    const unsigned* __restrict__ Wf = g_wf[layer];

    // ---- load B: (K/2)*128 uints, uint4 per thread ----
    {
        int total4 = (K >> 1) * 32;   // uint4 count
        for (int u = tid; u < total4; u += 256) {
            int k2 = u >> 5, n4 = (u & 31) * 4;
            uint4 v = *(const uint4*)&Wf[k2 * 128 + n4];
            sB[k2 * SBW + n4 + 0] = v.x;
            sB[k2 * SBW + n4 + 1] = v.y;
            sB[k2 * SBW + n4 + 2] = v.z;
            sB[k2 * SBW + n4 + 3] = v.w;
        }
    }
    // ---- load A: 64 rows x K ----
    if (A_in) {
        // fp32 input (layer 1, K=96), float4 per thread, no BN
        int n4 = K >> 2;
        int total = 64 * n4;
        for (int u = tid; u < total; u += 256) {
            int m = u / n4, kv4 = u - m * n4, gm = row0 + m;
            float4 v = make_float4(0.f, 0.f, 0.f, 0.f);
            if (gm < M) v = *(const float4*)&A_in[(size_t)gm * K + kv4 * 4];
            __half2 p0 = __floats2half2_rn(v.x, v.y);
            __half2 p1 = __floats2half2_rn(v.z, v.w);
            sA[(kv4 * 2 + 0) * SAW + m] = *reinterpret_cast<unsigned*>(&p0);
            sA[(kv4 * 2 + 1) * SAW + m] = *reinterpret_cast<unsigned*>(&p1);
        }
    } else {
        // fp16 g_agg input (layers 2/3, K=128), uint4 (8 halfs) per thread, BN+ReLU
        for (int u = tid; u < 1024; u += 256) {
            int m = u >> 4, seg = u & 15, gm = row0 + m;
            uint4 v = make_uint4(0u, 0u, 0u, 0u);
            if (gm < M) v = *(const uint4*)&g_agg[(size_t)gm * 128 + seg * 8];
            unsigned w[4] = {v.x, v.y, v.z, v.w};
            #pragma unroll
            for (int q = 0; q < 4; q++) {
                int k2 = seg * 4 + q;
                float2 f = __half22float2(*reinterpret_cast<__half2*>(&w[q]));
                f.x = fmaxf(fmaf(f.x, sa[2 * k2], sc[2 * k2]), 0.f);
                f.y = fmaxf(fmaf(f.y, sa[2 * k2 + 1], sc[2 * k2 + 1]), 0.f);
                __half2 p = __floats2half2_rn(f.x, f.y);
                sA[k2 * SAW + m] = *reinterpret_cast<unsigned*>(&p);
            }
        }
    }
    __syncthreads();

    float acc[2][4][4];
    #pragma unroll
    for (int mi = 0; mi < 2; mi++)
        #pragma unroll
        for (int ni = 0; ni < 4; ni++)
            #pragma unroll
            for (int q = 0; q < 4; q++) acc[mi][ni][q] = 0.f;

    int kq = lane & 3;
    const int nt = K >> 4;
    for (int kt = 0; kt < nt; kt++) {
        int k2b = kt * 8 + kq;
        unsigned ah[2][4];
        #pragma unroll
        for (int mi = 0; mi < 2; mi++) {
            int r = wm + mi * 16 + (lane >> 2);
            ah[mi][0] = sA[k2b * SAW + r];
            ah[mi][1] = sA[k2b * SAW + r + 8];
            ah[mi][2] = sA[(k2b + 4) * SAW + r];
            ah[mi][3] = sA[(k2b + 4) * SAW + r + 8];
        }
        #pragma unroll
        for (int ni = 0; ni < 4; ni++) {
            int n = wn + ni * 8 + (lane >> 2);
            unsigned b0 = sB[k2b * SBW + n], b1 = sB[(k2b + 4) * SBW + n];
            #pragma unroll
            for (int mi = 0; mi < 2; mi++)
                MMA_FP16(acc[mi][ni], ah[mi][0], ah[mi][1], ah[mi][2], ah[mi][3], b0, b1);
        }
    }

    // ---- epilogue: store fp16 (half2), no scaling ----
    #pragma unroll
    for (int mi = 0; mi < 2; mi++) {
        int r0 = row0 + wm + mi * 16 + (lane >> 2);
        int r1 = r0 + 8;
        #pragma unroll
        for (int ni = 0; ni < 4; ni++) {
            int nc = wn + ni * 8 + (lane & 3) * 2;
            if (r0 < M)
                *(__half2*)&g_hs[(size_t)r0 * 128 + nc] =
                    __floats2half2_rn(acc[mi][ni][0], acc[mi][ni][1]);
            if (r1 < M)
                *(__half2*)&g_hs[(size_t)r1 * 128 + nc] =
                    __floats2half2_rn(acc[mi][ni][2], acc[mi][ni][3]);
        }
    }
}

// ---------------- aggregation + BN stats (4 nodes/warp, dinv applied here) ---
__device__ __forceinline__ void acc_u2s(float4& a, uint2 u, float s) {
    float2 f0 = __half22float2(*reinterpret_cast<__half2*>(&u.x));
    float2 f1 = __half22float2(*reinterpret_cast<__half2*>(&u.y));
    a.x = fmaf(f0.x, s, a.x); a.y = fmaf(f0.y, s, a.y);
    a.z = fmaf(f1.x, s, a.z); a.w = fmaf(f1.y, s, a.w);
}

__global__ void k_agg(const float* __restrict__ b,
                      float* __restrict__ gsum, float* __restrict__ gsq) {
    __shared__ float s_sum[128];
    __shared__ float s_sq[128];
    if (threadIdx.x < 128) { s_sum[threadIdx.x] = 0.f; s_sq[threadIdx.x] = 0.f; }
    __syncthreads();

    int warp = threadIdx.x >> 5;
    int lane = threadIdx.x & 31;
    const uint2* __restrict__ hs2 = (const uint2*)g_hs;   // 32 uint2 per row
    float4 bb = ((const float4*)b)[lane];
    float4 ss = make_float4(0, 0, 0, 0), qq = make_float4(0, 0, 0, 0);

    int i0 = (blockIdx.x * 8 + warp) * 4;
    #pragma unroll
    for (int t = 0; t < 4; t++) {
        int i = i0 + t;
        if (i >= NN) break;
        float dv = g_dinv[i];
        float4 a0 = make_float4(0, 0, 0, 0);
        float4 a1 = make_float4(0, 0, 0, 0);
        float4 a2 = make_float4(0, 0, 0, 0);
        float4 a3 = make_float4(0, 0, 0, 0);
        acc_u2s(a0, hs2[(size_t)i * 32 + lane], dv);   // self term (dinv[i]*h[i])
        int s = g_rowptr[i], e = g_rowptr[i + 1];
        int j = s;
        for (; j + 4 <= e; j += 4) {
            int c0 = g_col[j], c1 = g_col[j + 1], c2 = g_col[j + 2], c3 = g_col[j + 3];
            float d0 = g_dinv[c0], d1 = g_dinv[c1], d2 = g_dinv[c2], d3 = g_dinv[c3];
            uint2 v0 = hs2[(size_t)c0 * 32 + lane];
            uint2 v1 = hs2[(size_t)c1 * 32 + lane];
            uint2 v2 = hs2[(size_t)c2 * 32 + lane];
            uint2 v3 = hs2[(size_t)c3 * 32 + lane];
            acc_u2s(a0, v0, d0); acc_u2s(a1, v1, d1);
            acc_u2s(a2, v2, d2); acc_u2s(a3, v3, d3);
        }
        for (; j < e; j++) {
            int c = g_col[j];
            acc_u2s(a0, hs2[(size_t)c * 32 + lane], g_dinv[c]);
        }
        float4 o;
        o.x = dv * ((a0.x + a1.x) + (a2.x + a3.x)) + bb.x;
        o.y = dv * ((a0.y + a1.y) + (a2.y + a3.y)) + bb.y;
        o.z = dv * ((a0.z + a1.z) + (a2.z + a3.z)) + bb.z;
        o.w = dv * ((a0.w + a1.w) + (a2.w + a3.w)) + bb.w;
        __half2 p0 = __floats2half2_rn(o.x, o.y);
        __half2 p1 = __floats2half2_rn(o.z, o.w);
        uint2 st;
        st.x = *reinterpret_cast<unsigned*>(&p0);
        st.y = *reinterpret_cast<unsigned*>(&p1);
        ((uint2*)g_agg)[(size_t)i * 32 + lane] = st;
        ss.x += o.x; ss.y += o.y; ss.z += o.z; ss.w += o.w;
        qq.x += o.x * o.x; qq.y += o.y * o.y; qq.z += o.z * o.z; qq.w += o.w * o.w;
    }

    int f = lane * 4;
    atomicAdd(&s_sum[f + 0], ss.x); atomicAdd(&s_sq[f + 0], qq.x);
    atomicAdd(&s_sum[f + 1], ss.y); atomicAdd(&s_sq[f + 1], qq.y);
    atomicAdd(&s_sum[f + 2], ss.z); atomicAdd(&s_sq[f + 2], qq.z);
    atomicAdd(&s_sum[f + 3], ss.w); atomicAdd(&s_sq[f + 3], qq.w);
    __syncthreads();
    if (threadIdx.x < 128) {
        atomicAdd(&gsum[threadIdx.x], s_sum[threadIdx.x]);
        atomicAdd(&gsq[threadIdx.x], s_sq[threadIdx.x]);
    }
}

// ---------------- fused pool + FC (one block per graph, MLP-4 gather) --------
__global__ __launch_bounds__(256) void k_poolfc(
    const int* __restrict__ batch,
    const float* __restrict__ gsum, const float* __restrict__ gsq,
    const float* __restrict__ gamma, const float* __restrict__ beta,
    const float* __restrict__ Wf1, const float* __restrict__ bf1,
    const float* __restrict__ Wf2, const float* __restrict__ bf2,
    float* __restrict__ out) {
    __shared__ float sa[128], sc[128];
    __shared__ float red[8][128];
    __shared__ float sp[128];
    __shared__ float sz[256];
    __shared__ int s_lo, s_hi;

    int t = threadIdx.x, g = blockIdx.x;
    int lane = t & 31, warp = t >> 5;

    if (t < 128) {
        float mean = gsum[t] * (1.0f / (float)NN);
        float var = gsq[t] * (1.0f / (float)NN) - mean * mean;
        float a = gamma[t] * rsqrtf(var + BN_EPS);
        sa[t] = a;
        sc[t] = beta[t] - mean * a;
    }
    if (t == 0) {
        int lo = 0, hi = NN;
        while (lo < hi) { int m = (lo + hi) >> 1; if (batch[m] < g) lo = m + 1; else hi = m; }
        s_lo = lo;
        lo = 0; hi = NN;
        while (lo < hi) { int m = (lo + hi) >> 1; if (batch[m] < g + 1) lo = m + 1; else hi = m; }
        s_hi = lo;
    }
    __syncthreads();

    int lo = s_lo, hi = s_hi;
    int f = lane * 4;
    float a0 = sa[f + 0], a1 = sa[f + 1], a2 = sa[f + 2], a3 = sa[f + 3];
    float c0 = sc[f + 0], c1 = sc[f + 1], c2 = sc[f + 2], c3 = sc[f + 3];

    float4 pacc[4];
    #pragma unroll
    for (int u = 0; u < 4; u++) pacc[u] = make_float4(0, 0, 0, 0);
    for (int base = lo + warp; base < hi; base += 32) {
        #pragma unroll
        for (int u = 0; u < 4; u++) {
            int i = base + u * 8;
            if (i < hi) {
                uint2 v = ((const uint2*)g_agg)[(size_t)i * 32 + lane];
                float2 x0 = __half22float2(*reinterpret_cast<__half2*>(&v.x));
                float2 x1 = __half22float2(*reinterpret_cast<__half2*>(&v.y));
                pacc[u].x += fmaxf(fmaf(x0.x, a0, c0), 0.f);
                pacc[u].y += fmaxf(fmaf(x0.y, a1, c1), 0.f);
                pacc[u].z += fmaxf(fmaf(x1.x, a2, c2), 0.f);
                pacc[u].w += fmaxf(fmaf(x1.y, a3, c3), 0.f);
            }
        }
    }
    float4 acc;
    acc.x = (pacc[0].x + pacc[1].x) + (pacc[2].x + pacc[3].x);
    acc.y = (pacc[0].y + pacc[1].y) + (pacc[2].y + pacc[3].y);
    acc.z = (pacc[0].z + pacc[1].z) + (pacc[2].z + pacc[3].z);
    acc.w = (pacc[0].w + pacc[1].w) + (pacc[2].w + pacc[3].w);
    red[warp][f + 0] = acc.x;
    red[warp][f + 1] = acc.y;
    red[warp][f + 2] = acc.z;
    red[warp][f + 3] = acc.w;
    __syncthreads();

    if (t < 128) {
        float s = 0.f;
        #pragma unroll
        for (int w = 0; w < 8; w++) s += red[w][t];
        float cnt = fmaxf((float)(hi - lo), 1.0f);
        sp[t] = s / cnt;
    }
    __syncthreads();

    float accf = bf1[t];
    #pragma unroll 8
    for (int k = 0; k < 128; k++) accf = fmaf(sp[k], Wf1[k * 256 + t], accf);
    sz[t] = fmaxf(accf, 0.f);
    __syncthreads();
    if (t < 10) {
        float o = bf2[t];
        #pragma unroll 8
        for (int k = 0; k < 256; k++) o = fmaf(sz[k], Wf2[k * 10 + t], o);
        out[g * 10 + t] = o;
    }
}

// ---------------- launch ------------------------------------------------------
extern "C" void kernel_launch(void* const* d_in, const int* in_sizes, int n_in,
                              void* d_out, int out_size) {
    const float* x     = (const float*)d_in[0];
    const int*   ei    = (const int*)d_in[1];
    const int*   batch = (const int*)d_in[2];
    const float* W1 = (const float*)d_in[3];
    const float* b1 = (const float*)d_in[4];
    const float* g1 = (const float*)d_in[5];
    const float* be1 = (const float*)d_in[6];
    const float* W2 = (const float*)d_in[7];
    const float* b2 = (const float*)d_in[8];
    const float* g2 = (const float*)d_in[9];
    const float* be2 = (const float*)d_in[10];
    const float* W3 = (const float*)d_in[11];
    const float* b3 = (const float*)d_in[12];
    const float* g3 = (const float*)d_in[13];
    const float* be3 = (const float*)d_in[14];
    const float* Wf1 = (const float*)d_in[15];
    const float* bf1 = (const float*)d_in[16];
    const float* Wf2 = (const float*)d_in[17];
    const float* bf2 = (const float*)d_in[18];
    float* out = (float*)d_out;

    const int* src = ei;
    const int* dst = ei + EE;

    static cudaStream_t sGraph = nullptr;
    static cudaEvent_t evFork = nullptr, evJoin = nullptr;
    static int once = 0;
    if (!once) {
        cudaStreamCreateWithFlags(&sGraph, cudaStreamNonBlocking);
        cudaEventCreateWithFlags(&evFork, cudaEventDisableTiming);
        cudaEventCreateWithFlags(&evJoin, cudaEventDisableTiming);
        cudaFuncSetAttribute(k_gemm, cudaFuncAttributeMaxDynamicSharedMemorySize, GEMM_SMEM);
        once = 1;
    }

    float* sum0; float* sq0; float* sum1; float* sq1; float* sum2; float* sq2;
    cudaGetSymbolAddress((void**)&sum0, g_sumA);
    cudaGetSymbolAddress((void**)&sq0, g_sqA);
    sum1 = sum0 + 128; sum2 = sum0 + 256;
    sq1 = sq0 + 128; sq2 = sq0 + 256;

    const int gemm_grid = (NN + 63) / 64;
    const int agg_grid = (NN + 31) / 32;

    // ---- fork: graph preprocessing (stream sGraph) || W-pack + GEMM L1 (0) ----
    cudaEventRecord(evFork, 0);
    cudaStreamWaitEvent(sGraph, evFork, 0);

    k_deg_count<<<(EE + 255) / 256, 256, 0, sGraph>>>(dst);
    k_scan<<<1, 1024, 0, sGraph>>>();
    k_fill<<<(EE + 255) / 256, 256, 0, sGraph>>>(src, dst);
    cudaEventRecord(evJoin, sGraph);

    k_init<<<(6144 + 16384 + 255) / 256, 256>>>(W1, W2, W3);
    k_gemm<<<gemm_grid, 256, GEMM_SMEM>>>(x, 0, NN, 96, nullptr, nullptr, nullptr, nullptr);

    cudaStreamWaitEvent(0, evJoin, 0);

    // ---- layers (default stream) ----
    k_agg<<<agg_grid, 256>>>(b1, sum0, sq0);

    k_gemm<<<gemm_grid, 256, GEMM_SMEM>>>(nullptr, 1, NN, 128, sum0, sq0, g1, be1);
    k_agg<<<agg_grid, 256>>>(b2, sum1, sq1);

    k_gemm<<<gemm_grid, 256, GEMM_SMEM>>>(nullptr, 2, NN, 128, sum1, sq1, g2, be2);
    k_agg<<<agg_grid, 256>>>(b3, sum2, sq2);

    k_poolfc<<<GG, 256>>>(batch, sum2, sq2, g3, be3, Wf1, bf1, Wf2, bf2, out);
}

// round 10
// speedup vs baseline: 1.3448x; 1.3448x over previous
#include <cuda_runtime.h>
#include <cuda_bf16.h>
#include <cuda_fp16.h>
#include <cstdint>

#define NN 50000
#define EE 800000
#define GG 64
#define BN_EPS 1e-5f

// ---------------- scratch (static device globals; no allocation) ------------
__device__ __half g_hs[(size_t)NN * 128];   // GEMM output (pre-scaled by dinv), fp16
__device__ __half g_agg[(size_t)NN * 128];  // aggregated output (pre-BN), fp16
__device__ float g_dinv[NN];
__device__ int   g_deg[NN];                 // zero-init at load; k_scan re-zeroes
__device__ int   g_rowptr[NN + 1];
__device__ int   g_cursor[NN];
__device__ int   g_col[EE];
__device__ float g_sumA[3][128], g_sqA[3][128];
// pre-converted weights: [layer][k2*128 + n], half2 packed over (k=2*k2, 2*k2+1)
__device__ unsigned g_wf[3][64 * 128];

// ---------------- init: zero stats + W fp16 pre-pack -------------------------
__global__ void k_init(const float* __restrict__ W1, const float* __restrict__ W2,
                       const float* __restrict__ W3) {
    int i = blockIdx.x * blockDim.x + threadIdx.x;
    if (i < 128) {
        #pragma unroll
        for (int l = 0; l < 3; l++) { g_sumA[l][i] = 0.f; g_sqA[l][i] = 0.f; }
    }
    // W pack: layer0 48*128, layer1/2 64*128 packed k-pair elements
    int l = -1, idx = 0;
    const float* W = nullptr;
    if (i < 6144) { l = 0; idx = i; W = W1; }
    else if (i < 6144 + 8192) { l = 1; idx = i - 6144; W = W2; }
    else if (i < 6144 + 16384) { l = 2; idx = i - 14336; W = W3; }
    if (l >= 0) {
        int k2 = idx >> 7, n = idx & 127;
        float w0 = W[(size_t)(2 * k2) * 128 + n];
        float w1 = W[(size_t)(2 * k2 + 1) * 128 + n];
        __half2 p = __floats2half2_rn(w0, w1);
        g_wf[l][idx] = *reinterpret_cast<unsigned*>(&p);
    }
}

__global__ void k_deg_count(const int* __restrict__ dst) {
    int e = blockIdx.x * blockDim.x + threadIdx.x;
    if (e < EE) atomicAdd(&g_deg[dst[e]], 1);
}

// 1024-thread scan; also computes dinv and RE-ZEROES g_deg for the next call
__global__ void k_scan() {
    __shared__ int part[1024];
    const int CH = (NN + 1023) / 1024;
    int t = threadIdx.x;
    int s = 0;
    for (int j = 0; j < CH; j++) {
        int i = t * CH + j;
        if (i < NN) s += g_deg[i];
    }
    part[t] = s;
    __syncthreads();
    int own = s;
    #pragma unroll
    for (int off = 1; off < 1024; off <<= 1) {
        int v = 0;
        if (t >= off) v = part[t - off];
        __syncthreads();
        if (t >= off) part[t] += v;
        __syncthreads();
    }
    int run = part[t] - own;
    for (int j = 0; j < CH; j++) {
        int i = t * CH + j;
        if (i < NN) {
            int d = g_deg[i];
            g_cursor[i] = run;
            run += d;
            g_rowptr[i + 1] = run;
            g_dinv[i] = rsqrtf((float)d + 1.0f);   // +1 self loop
            g_deg[i] = 0;                          // keep zero-invariant
        }
    }
    if (t == 0) g_rowptr[0] = 0;
}

__global__ void k_fill(const int* __restrict__ src, const int* __restrict__ dst) {
    int e = blockIdx.x * blockDim.x + threadIdx.x;
    if (e < EE) {
        int d = dst[e];
        int p = atomicAdd(&g_cursor[d], 1);
        g_col[p] = src[e];
    }
}

// ---------------- GEMM (fp16, m16n8k16, whole-K in smem, ONE sync) -----------
// hs[m,:] = fp16( (relu(bn(A[m,:])) @ W) * dinv[m] )
// Block tile 64(M) x 128(N) x K, 256 threads (8 warps: 2M x 4N, warp 32x32).

#define MMA_FP16(C, a0, a1, a2, a3, b0, b1)                                        \
    asm volatile(                                                                  \
        "mma.sync.aligned.m16n8k16.row.col.f32.f16.f16.f32 "                       \
        "{%0,%1,%2,%3},{%4,%5,%6,%7},{%8,%9},{%0,%1,%2,%3};"                       \
        : "+f"((C)[0]), "+f"((C)[1]), "+f"((C)[2]), "+f"((C)[3])                   \
        : "r"(a0), "r"(a1), "r"(a2), "r"(a3), "r"(b0), "r"(b1))

#define SAW 72    // A stride (64 rows + 8 pad), ≡8 mod 32 → conflict-free
#define SBW 136   // B stride (128 cols + 8 pad)
#define GEMM_SMEM ((64 * SAW + 64 * SBW) * 4)

__global__ __launch_bounds__(256) void k_gemm(
    const float* __restrict__ A_in, int layer, int M, int K,
    const float* __restrict__ gsum, const float* __restrict__ gsq,
    const float* __restrict__ gamma, const float* __restrict__ beta) {
    extern __shared__ unsigned smem_u[];
    unsigned* sA = smem_u;              // [K/2][64] stride SAW
    unsigned* sB = smem_u + 64 * SAW;   // [K/2][128] stride SBW
    __shared__ float sa[128], sc[128];

    int tid = threadIdx.x, lane = tid & 31, warp = tid >> 5;
    int use_bn = (gsum != nullptr);
    if (use_bn && tid < 128) {
        float mean = gsum[tid] * (1.0f / (float)NN);
        float var = gsq[tid] * (1.0f / (float)NN) - mean * mean;
        float a = gamma[tid] * rsqrtf(var + BN_EPS);
        sa[tid] = a;
        sc[tid] = beta[tid] - mean * a;
    }
    __syncthreads();

    int row0 = blockIdx.x * 64;
    int wm = (warp >> 2) * 32;     // 2 M groups
    int wn = (warp & 3) * 32;      // 4 N groups
    const unsigned* __restrict__ Wf = g_wf[layer];

    // ---- load B: (K/2)*128 uints, uint4 per thread ----
    {
        int total4 = (K >> 1) * 32;   // uint4 count
        for (int u = tid; u < total4; u += 256) {
            int k2 = u >> 5, n4 = (u & 31) * 4;
            uint4 v = *(const uint4*)&Wf[k2 * 128 + n4];
            sB[k2 * SBW + n4 + 0] = v.x;
            sB[k2 * SBW + n4 + 1] = v.y;
            sB[k2 * SBW + n4 + 2] = v.z;
            sB[k2 * SBW + n4 + 3] = v.w;
        }
    }
    // ---- load A: 64 rows x K ----
    if (A_in) {
        // fp32 input (layer 1, K=96), float4 per thread, no BN
        int n4 = K >> 2;
        int total = 64 * n4;
        for (int u = tid; u < total; u += 256) {
            int m = u / n4, kv4 = u - m * n4, gm = row0 + m;
            float4 v = make_float4(0.f, 0.f, 0.f, 0.f);
            if (gm < M) v = *(const float4*)&A_in[(size_t)gm * K + kv4 * 4];
            __half2 p0 = __floats2half2_rn(v.x, v.y);
            __half2 p1 = __floats2half2_rn(v.z, v.w);
            sA[(kv4 * 2 + 0) * SAW + m] = *reinterpret_cast<unsigned*>(&p0);
            sA[(kv4 * 2 + 1) * SAW + m] = *reinterpret_cast<unsigned*>(&p1);
        }
    } else {
        // fp16 g_agg input (layers 2/3, K=128), uint4 (8 halfs) per thread, BN+ReLU
        for (int u = tid; u < 1024; u += 256) {
            int m = u >> 4, seg = u & 15, gm = row0 + m;
            uint4 v = make_uint4(0u, 0u, 0u, 0u);
            if (gm < M) v = *(const uint4*)&g_agg[(size_t)gm * 128 + seg * 8];
            unsigned w[4] = {v.x, v.y, v.z, v.w};
            #pragma unroll
            for (int q = 0; q < 4; q++) {
                int k2 = seg * 4 + q;
                float2 f = __half22float2(*reinterpret_cast<__half2*>(&w[q]));
                f.x = fmaxf(fmaf(f.x, sa[2 * k2], sc[2 * k2]), 0.f);
                f.y = fmaxf(fmaf(f.y, sa[2 * k2 + 1], sc[2 * k2 + 1]), 0.f);
                __half2 p = __floats2half2_rn(f.x, f.y);
                sA[k2 * SAW + m] = *reinterpret_cast<unsigned*>(&p);
            }
        }
    }
    __syncthreads();

    float acc[2][4][4];
    #pragma unroll
    for (int mi = 0; mi < 2; mi++)
        #pragma unroll
        for (int ni = 0; ni < 4; ni++)
            #pragma unroll
            for (int q = 0; q < 4; q++) acc[mi][ni][q] = 0.f;

    int kq = lane & 3;
    const int nt = K >> 4;
    for (int kt = 0; kt < nt; kt++) {
        int k2b = kt * 8 + kq;
        unsigned ah[2][4];
        #pragma unroll
        for (int mi = 0; mi < 2; mi++) {
            int r = wm + mi * 16 + (lane >> 2);
            ah[mi][0] = sA[k2b * SAW + r];
            ah[mi][1] = sA[k2b * SAW + r + 8];
            ah[mi][2] = sA[(k2b + 4) * SAW + r];
            ah[mi][3] = sA[(k2b + 4) * SAW + r + 8];
        }
        #pragma unroll
        for (int ni = 0; ni < 4; ni++) {
            int n = wn + ni * 8 + (lane >> 2);
            unsigned b0 = sB[k2b * SBW + n], b1 = sB[(k2b + 4) * SBW + n];
            #pragma unroll
            for (int mi = 0; mi < 2; mi++)
                MMA_FP16(acc[mi][ni], ah[mi][0], ah[mi][1], ah[mi][2], ah[mi][3], b0, b1);
        }
    }

    // ---- epilogue: scale by dinv[row], store fp16 (half2) ----
    #pragma unroll
    for (int mi = 0; mi < 2; mi++) {
        int r0 = row0 + wm + mi * 16 + (lane >> 2);
        int r1 = r0 + 8;
        float d0 = (r0 < M) ? g_dinv[r0] : 0.f;
        float d1 = (r1 < M) ? g_dinv[r1] : 0.f;
        #pragma unroll
        for (int ni = 0; ni < 4; ni++) {
            int nc = wn + ni * 8 + (lane & 3) * 2;
            if (r0 < M)
                *(__half2*)&g_hs[(size_t)r0 * 128 + nc] =
                    __floats2half2_rn(acc[mi][ni][0] * d0, acc[mi][ni][1] * d0);
            if (r1 < M)
                *(__half2*)&g_hs[(size_t)r1 * 128 + nc] =
                    __floats2half2_rn(acc[mi][ni][2] * d1, acc[mi][ni][3] * d1);
        }
    }
}

// ---------------- aggregation + BN stats (4 nodes per warp, fp16 gather) ----
__device__ __forceinline__ void acc_u2(float4& a, uint2 u) {
    float2 f0 = __half22float2(*reinterpret_cast<__half2*>(&u.x));
    float2 f1 = __half22float2(*reinterpret_cast<__half2*>(&u.y));
    a.x += f0.x; a.y += f0.y; a.z += f1.x; a.w += f1.y;
}

__global__ void k_agg(const float* __restrict__ b,
                      float* __restrict__ gsum, float* __restrict__ gsq) {
    __shared__ float s_sum[128];
    __shared__ float s_sq[128];
    if (threadIdx.x < 128) { s_sum[threadIdx.x] = 0.f; s_sq[threadIdx.x] = 0.f; }
    __syncthreads();

    int warp = threadIdx.x >> 5;
    int lane = threadIdx.x & 31;
    const uint2* __restrict__ hs2 = (const uint2*)g_hs;   // 32 uint2 per row
    float4 bb = ((const float4*)b)[lane];
    float4 ss = make_float4(0, 0, 0, 0), qq = make_float4(0, 0, 0, 0);

    int i0 = (blockIdx.x * 8 + warp) * 4;
    #pragma unroll
    for (int t = 0; t < 4; t++) {
        int i = i0 + t;
        if (i >= NN) break;
        float4 a0 = make_float4(0, 0, 0, 0);
        float4 a1 = make_float4(0, 0, 0, 0);
        float4 a2 = make_float4(0, 0, 0, 0);
        float4 a3 = make_float4(0, 0, 0, 0);
        acc_u2(a0, hs2[(size_t)i * 32 + lane]);   // self term
        int s = g_rowptr[i], e = g_rowptr[i + 1];
        int j = s;
        for (; j + 4 <= e; j += 4) {
            int c0 = g_col[j], c1 = g_col[j + 1], c2 = g_col[j + 2], c3 = g_col[j + 3];
            uint2 v0 = hs2[(size_t)c0 * 32 + lane];
            uint2 v1 = hs2[(size_t)c1 * 32 + lane];
            uint2 v2 = hs2[(size_t)c2 * 32 + lane];
            uint2 v3 = hs2[(size_t)c3 * 32 + lane];
            acc_u2(a0, v0); acc_u2(a1, v1); acc_u2(a2, v2); acc_u2(a3, v3);
        }
        for (; j < e; j++) {
            int c = g_col[j];
            acc_u2(a0, hs2[(size_t)c * 32 + lane]);
        }
        float di = g_dinv[i];
        float4 o;
        o.x = di * ((a0.x + a1.x) + (a2.x + a3.x)) + bb.x;
        o.y = di * ((a0.y + a1.y) + (a2.y + a3.y)) + bb.y;
        o.z = di * ((a0.z + a1.z) + (a2.z + a3.z)) + bb.z;
        o.w = di * ((a0.w + a1.w) + (a2.w + a3.w)) + bb.w;
        __half2 p0 = __floats2half2_rn(o.x, o.y);
        __half2 p1 = __floats2half2_rn(o.z, o.w);
        uint2 st;
        st.x = *reinterpret_cast<unsigned*>(&p0);
        st.y = *reinterpret_cast<unsigned*>(&p1);
        ((uint2*)g_agg)[(size_t)i * 32 + lane] = st;
        ss.x += o.x; ss.y += o.y; ss.z += o.z; ss.w += o.w;
        qq.x += o.x * o.x; qq.y += o.y * o.y; qq.z += o.z * o.z; qq.w += o.w * o.w;
    }

    int f = lane * 4;
    atomicAdd(&s_sum[f + 0], ss.x); atomicAdd(&s_sq[f + 0], qq.x);
    atomicAdd(&s_sum[f + 1], ss.y); atomicAdd(&s_sq[f + 1], qq.y);
    atomicAdd(&s_sum[f + 2], ss.z); atomicAdd(&s_sq[f + 2], qq.z);
    atomicAdd(&s_sum[f + 3], ss.w); atomicAdd(&s_sq[f + 3], qq.w);
    __syncthreads();
    if (threadIdx.x < 128) {
        atomicAdd(&gsum[threadIdx.x], s_sum[threadIdx.x]);
        atomicAdd(&gsq[threadIdx.x], s_sq[threadIdx.x]);
    }
}

// ---------------- fused pool + FC (one block per graph, MLP-4 gather) --------
__global__ __launch_bounds__(256) void k_poolfc(
    const int* __restrict__ batch,
    const float* __restrict__ gsum, const float* __restrict__ gsq,
    const float* __restrict__ gamma, const float* __restrict__ beta,
    const float* __restrict__ Wf1, const float* __restrict__ bf1,
    const float* __restrict__ Wf2, const float* __restrict__ bf2,
    float* __restrict__ out) {
    __shared__ float sa[128], sc[128];
    __shared__ float red[8][128];
    __shared__ float sp[128];
    __shared__ float sz[256];
    __shared__ int s_lo, s_hi;

    int t = threadIdx.x, g = blockIdx.x;
    int lane = t & 31, warp = t >> 5;

    if (t < 128) {
        float mean = gsum[t] * (1.0f / (float)NN);
        float var = gsq[t] * (1.0f / (float)NN) - mean * mean;
        float a = gamma[t] * rsqrtf(var + BN_EPS);
        sa[t] = a;
        sc[t] = beta[t] - mean * a;
    }
    if (t == 0) {
        int lo = 0, hi = NN;
        while (lo < hi) { int m = (lo + hi) >> 1; if (batch[m] < g) lo = m + 1; else hi = m; }
        s_lo = lo;
        lo = 0; hi = NN;
        while (lo < hi) { int m = (lo + hi) >> 1; if (batch[m] < g + 1) lo = m + 1; else hi = m; }
        s_hi = lo;
    }
    __syncthreads();

    int lo = s_lo, hi = s_hi;
    int f = lane * 4;
    float a0 = sa[f + 0], a1 = sa[f + 1], a2 = sa[f + 2], a3 = sa[f + 3];
    float c0 = sc[f + 0], c1 = sc[f + 1], c2 = sc[f + 2], c3 = sc[f + 3];

    float4 pacc[4];
    #pragma unroll
    for (int u = 0; u < 4; u++) pacc[u] = make_float4(0, 0, 0, 0);
    for (int base = lo + warp; base < hi; base += 32) {
        #pragma unroll
        for (int u = 0; u < 4; u++) {
            int i = base + u * 8;
            if (i < hi) {
                uint2 v = ((const uint2*)g_agg)[(size_t)i * 32 + lane];
                float2 x0 = __half22float2(*reinterpret_cast<__half2*>(&v.x));
                float2 x1 = __half22float2(*reinterpret_cast<__half2*>(&v.y));
                pacc[u].x += fmaxf(fmaf(x0.x, a0, c0), 0.f);
                pacc[u].y += fmaxf(fmaf(x0.y, a1, c1), 0.f);
                pacc[u].z += fmaxf(fmaf(x1.x, a2, c2), 0.f);
                pacc[u].w += fmaxf(fmaf(x1.y, a3, c3), 0.f);
            }
        }
    }
    float4 acc;
    acc.x = (pacc[0].x + pacc[1].x) + (pacc[2].x + pacc[3].x);
    acc.y = (pacc[0].y + pacc[1].y) + (pacc[2].y + pacc[3].y);
    acc.z = (pacc[0].z + pacc[1].z) + (pacc[2].z + pacc[3].z);
    acc.w = (pacc[0].w + pacc[1].w) + (pacc[2].w + pacc[3].w);
    red[warp][f + 0] = acc.x;
    red[warp][f + 1] = acc.y;
    red[warp][f + 2] = acc.z;
    red[warp][f + 3] = acc.w;
    __syncthreads();

    if (t < 128) {
        float s = 0.f;
        #pragma unroll
        for (int w = 0; w < 8; w++) s += red[w][t];
        float cnt = fmaxf((float)(hi - lo), 1.0f);
        sp[t] = s / cnt;
    }
    __syncthreads();

    float accf = bf1[t];
    #pragma unroll 8
    for (int k = 0; k < 128; k++) accf = fmaf(sp[k], Wf1[k * 256 + t], accf);
    sz[t] = fmaxf(accf, 0.f);
    __syncthreads();
    if (t < 10) {
        float o = bf2[t];
        #pragma unroll 8
        for (int k = 0; k < 256; k++) o = fmaf(sz[k], Wf2[k * 10 + t], o);
        out[g * 10 + t] = o;
    }
}

// ---------------- launch ------------------------------------------------------
extern "C" void kernel_launch(void* const* d_in, const int* in_sizes, int n_in,
                              void* d_out, int out_size) {
    const float* x     = (const float*)d_in[0];
    const int*   ei    = (const int*)d_in[1];
    const int*   batch = (const int*)d_in[2];
    const float* W1 = (const float*)d_in[3];
    const float* b1 = (const float*)d_in[4];
    const float* g1 = (const float*)d_in[5];
    const float* be1 = (const float*)d_in[6];
    const float* W2 = (const float*)d_in[7];
    const float* b2 = (const float*)d_in[8];
    const float* g2 = (const float*)d_in[9];
    const float* be2 = (const float*)d_in[10];
    const float* W3 = (const float*)d_in[11];
    const float* b3 = (const float*)d_in[12];
    const float* g3 = (const float*)d_in[13];
    const float* be3 = (const float*)d_in[14];
    const float* Wf1 = (const float*)d_in[15];
    const float* bf1 = (const float*)d_in[16];
    const float* Wf2 = (const float*)d_in[17];
    const float* bf2 = (const float*)d_in[18];
    float* out = (float*)d_out;

    const int* src = ei;
    const int* dst = ei + EE;

    static int once = 0;
    if (!once) {
        cudaFuncSetAttribute(k_gemm, cudaFuncAttributeMaxDynamicSharedMemorySize, GEMM_SMEM);
        once = 1;
    }

    float* sum0; float* sq0; float* sum1; float* sq1; float* sum2; float* sq2;
    cudaGetSymbolAddress((void**)&sum0, g_sumA);
    cudaGetSymbolAddress((void**)&sq0, g_sqA);
    sum1 = sum0 + 128; sum2 = sum0 + 256;
    sq1 = sq0 + 128; sq2 = sq0 + 256;

    const int gemm_grid = (NN + 63) / 64;
    const int agg_grid = (NN + 31) / 32;

    // preprocessing (single stream; k_gemm L1 is 4th launch → profiler window;
    // k_fill completes before k_agg L1 in stream order)
    k_init<<<(6144 + 16384 + 255) / 256, 256>>>(W1, W2, W3);
    k_deg_count<<<(EE + 255) / 256, 256>>>(dst);
    k_scan<<<1, 1024>>>();

    // layer 1 (K=96, input x, no BN)
    k_gemm<<<gemm_grid, 256, GEMM_SMEM>>>(x, 0, NN, 96, nullptr, nullptr, nullptr, nullptr);
    k_fill<<<(EE + 255) / 256, 256>>>(src, dst);
    k_agg<<<agg_grid, 256>>>(b1, sum0, sq0);

    // layer 2 (BN1+ReLU fused into A-load)
    k_gemm<<<gemm_grid, 256, GEMM_SMEM>>>(nullptr, 1, NN, 128, sum0, sq0, g1, be1);
    k_agg<<<agg_grid, 256>>>(b2, sum1, sq1);

    // layer 3
    k_gemm<<<gemm_grid, 256, GEMM_SMEM>>>(nullptr, 2, NN, 128, sum1, sq1, g2, be2);
    k_agg<<<agg_grid, 256>>>(b3, sum2, sq2);

    // fused pool (BN3+ReLU inline) + FC head
    k_poolfc<<<GG, 256>>>(batch, sum2, sq2, g3, be3, Wf1, bf1, Wf2, bf2, out);
}

// round 12
// speedup vs baseline: 1.7100x; 1.2715x over previous
#include <cuda_runtime.h>
#include <cuda_fp16.h>
#include <cstdint>

#define NN 50000
#define EE 800000
#define GG 64
#define BN_EPS 1e-5f
#define NTILE 782          // ceil(NN/64)
#define NAGG 1563          // ceil(NN/32)
#define SA 136             // smem stride (conflict-free)
#define DSM_BYTES 17408    // 4352 uints: 2-buf A (2176) + 2-buf B (2176)

// ---------------- device globals (no allocation) -----------------------------
__device__ __half g_hs[(size_t)NN * 128];   // GEMM out (dinv-scaled) fp16
__device__ __half g_agg[(size_t)NN * 128];  // aggregated (pre-BN) fp16
__device__ float g_dinv[NN];
__device__ int   g_deg[NN];                 // zero at load; re-zeroed each run
__device__ int   g_rowptr[NN + 1];
__device__ int   g_cursor[NN];
__device__ int   g_col[EE];
__device__ float g_sumA[3][128], g_sqA[3][128];
__device__ unsigned g_wf[3][64 * 128];      // packed half2 weights
__device__ int   g_bsum[2048], g_bsum2[2048];
__device__ unsigned g_barcnt;
__device__ volatile unsigned g_release;

// ---------------- init: reset barrier + stats, pack W ------------------------
__global__ void k_init(const float* __restrict__ W1, const float* __restrict__ W2,
                       const float* __restrict__ W3) {
    int i = blockIdx.x * blockDim.x + threadIdx.x;
    if (i == 0) { g_barcnt = 0; g_release = 0; }
    if (i < 128) {
        #pragma unroll
        for (int l = 0; l < 3; l++) { g_sumA[l][i] = 0.f; g_sqA[l][i] = 0.f; }
    }
    int l = -1, idx = 0;
    const float* W = nullptr;
    if (i < 6144) { l = 0; idx = i; W = W1; }
    else if (i < 6144 + 8192) { l = 1; idx = i - 6144; W = W2; }
    else if (i < 6144 + 16384) { l = 2; idx = i - 14336; W = W3; }
    if (l >= 0) {
        int k2 = idx >> 7, n = idx & 127;
        float w0 = W[(size_t)(2 * k2) * 128 + n];
        float w1 = W[(size_t)(2 * k2 + 1) * 128 + n];
        __half2 p = __floats2half2_rn(w0, w1);
        g_wf[l][idx] = *reinterpret_cast<unsigned*>(&p);
    }
}

// ---------------- grid barrier (all blocks resident) -------------------------
__device__ __forceinline__ void gsync(int phase, int nb) {
    __threadfence();
    __syncthreads();
    if (threadIdx.x == 0) {
        unsigned target = (unsigned)phase * (unsigned)nb;
        unsigned old = atomicAdd(&g_barcnt, 1u);
        if (old + 1u == target) {
            g_release = (unsigned)phase;
            __threadfence();
        } else {
            while (g_release < (unsigned)phase) __nanosleep(64);
            __threadfence();
        }
    }
    __syncthreads();
}

#define MMA_FP16(C, a0, a1, a2, a3, b0, b1)                                        \
    asm volatile(                                                                  \
        "mma.sync.aligned.m16n8k16.row.col.f32.f16.f16.f32 "                       \
        "{%0,%1,%2,%3},{%4,%5,%6,%7},{%8,%9},{%0,%1,%2,%3};"                       \
        : "+f"((C)[0]), "+f"((C)[1]), "+f"((C)[2]), "+f"((C)[3])                   \
        : "r"(a0), "r"(a1), "r"(a2), "r"(a3), "r"(b0), "r"(b1))

// ---------------- the fused persistent kernel --------------------------------
__global__ __launch_bounds__(256) void k_fused(
    const float* __restrict__ x,
    const int* __restrict__ src, const int* __restrict__ dst,
    const int* __restrict__ batch,
    const float* __restrict__ b1, const float* __restrict__ b2, const float* __restrict__ b3,
    const float* __restrict__ g1, const float* __restrict__ be1,
    const float* __restrict__ g2, const float* __restrict__ be2,
    const float* __restrict__ g3, const float* __restrict__ be3,
    const float* __restrict__ Wf1, const float* __restrict__ bf1,
    const float* __restrict__ Wf2, const float* __restrict__ bf2,
    float* __restrict__ out) {
    extern __shared__ unsigned dsm[];
    __shared__ float shA[128], shB[128];
    __shared__ int s_lo, s_hi;

    const int nb = gridDim.x;
    const int bid = blockIdx.x;
    const int tid = threadIdx.x, lane = tid & 31, warp = tid >> 5;
    int ph = 0;

    // ===== P0: degree count =====
    for (int e = bid * 256 + tid; e < EE; e += nb * 256)
        atomicAdd(&g_deg[dst[e]], 1);
    gsync(++ph, nb);

    // ===== P1: per-block partial sums of deg =====
    const int chunk = (NN + nb - 1) / nb;
    const int start = bid * chunk;
    const int end = (start + chunk < NN) ? start + chunk : NN;
    {
        int* part = (int*)dsm;
        int s = 0;
        for (int i = start + tid; i < end; i += 256) s += __ldcg(&g_deg[i]);
        part[tid] = s;
        __syncthreads();
        for (int off = 128; off; off >>= 1) {
            if (tid < off) part[tid] += part[tid + off];
            __syncthreads();
        }
        if (tid == 0) g_bsum[bid] = part[0];
    }
    gsync(++ph, nb);

    // ===== P2: block 0 exclusive-scans block sums =====
    if (bid == 0) {
        int* part = (int*)dsm;
        int CH2 = (nb + 255) / 256;
        int s = 0;
        for (int j = 0; j < CH2; j++) {
            int idx = tid * CH2 + j;
            if (idx < nb) s += __ldcg(&g_bsum[idx]);
        }
        part[tid] = s;
        __syncthreads();
        int own = s;
        for (int off = 1; off < 256; off <<= 1) {
            int v = 0;
            if (tid >= off) v = part[tid - off];
            __syncthreads();
            if (tid >= off) part[tid] += v;
            __syncthreads();
        }
        int run = part[tid] - own;
        for (int j = 0; j < CH2; j++) {
            int idx = tid * CH2 + j;
            if (idx < nb) { g_bsum2[idx] = run; run += __ldcg(&g_bsum[idx]); }
        }
    }
    gsync(++ph, nb);

    // ===== P3: finalize rowptr/cursor/dinv, re-zero deg =====
    {
        int* part = (int*)dsm;
        int base = __ldcg(&g_bsum2[bid]);
        int CHL = (chunk + 255) / 256;
        int s = 0;
        for (int j = 0; j < CHL; j++) {
            int i = start + tid * CHL + j;
            if (i < end) s += __ldcg(&g_deg[i]);
        }
        part[tid] = s;
        __syncthreads();
        int own = s;
        for (int off = 1; off < 256; off <<= 1) {
            int v = 0;
            if (tid >= off) v = part[tid - off];
            __syncthreads();
            if (tid >= off) part[tid] += v;
            __syncthreads();
        }
        int run = base + part[tid] - own;
        for (int j = 0; j < CHL; j++) {
            int i = start + tid * CHL + j;
            if (i < end) {
                int d = __ldcg(&g_deg[i]);
                g_cursor[i] = run;
                run += d;
                g_rowptr[i + 1] = run;
                g_dinv[i] = rsqrtf((float)d + 1.0f);
                g_deg[i] = 0;
            }
        }
        if (bid == 0 && tid == 0) g_rowptr[0] = 0;
    }
    gsync(++ph, nb);

    // ===== P4: fill CSR columns =====
    for (int e = bid * 256 + tid; e < EE; e += nb * 256) {
        int d = dst[e];
        int p = atomicAdd(&g_cursor[d], 1);
        g_col[p] = src[e];
    }
    gsync(++ph, nb);

    // ===== layers: GEMM -> aggregate, x3 =====
    for (int l = 0; l < 3; l++) {
        const int K = l ? 128 : 96;
        const int nt = K >> 4;
        const unsigned* __restrict__ Wf = g_wf[l];

        // BN coefficients for this layer's input (l>0)
        if (l > 0 && tid < 128) {
            float mean = __ldcg(&g_sumA[l - 1][tid]) * (1.0f / (float)NN);
            float var = __ldcg(&g_sqA[l - 1][tid]) * (1.0f / (float)NN) - mean * mean;
            const float* gm = (l == 1) ? g1 : g2;
            const float* bt = (l == 1) ? be1 : be2;
            float a = gm[tid] * rsqrtf(var + BN_EPS);
            shA[tid] = a;
            shB[tid] = bt[tid] - mean * a;
        }
        __syncthreads();

        // ---- GEMM tiles (64 rows each), double-buffered ----
        unsigned* sAb = dsm;          // 2 x 1088
        unsigned* sBb = dsm + 2176;   // 2 x 1088
        int wm = (warp >> 2) * 32;
        int wn = (warp & 3) * 32;
        for (int t = bid; t < NTILE; t += nb) {
            int row0 = t * 64;
            float acc[2][4][4];
            #pragma unroll
            for (int mi = 0; mi < 2; mi++)
                #pragma unroll
                for (int ni = 0; ni < 4; ni++)
                    #pragma unroll
                    for (int q = 0; q < 4; q++) acc[mi][ni][q] = 0.f;

            float ae[4];
            unsigned bs[4];

            auto LOADF = [&](int kt) {
                int k0 = kt * 16;
                int m = tid >> 2, kv = (tid & 3) * 4, gm = row0 + m;
                if (l == 0) {
                    float4 v = make_float4(0.f, 0.f, 0.f, 0.f);
                    if (gm < NN) v = *(const float4*)&x[(size_t)gm * 96 + k0 + kv];
                    ae[0] = v.x; ae[1] = v.y; ae[2] = v.z; ae[3] = v.w;
                } else {
                    uint2 hv = make_uint2(0u, 0u);
                    if (gm < NN) hv = __ldcg((const uint2*)&g_agg[(size_t)gm * 128 + k0 + kv]);
                    float2 f0 = __half22float2(*reinterpret_cast<__half2*>(&hv.x));
                    float2 f1 = __half22float2(*reinterpret_cast<__half2*>(&hv.y));
                    int kb = k0 + kv;
                    ae[0] = fmaxf(fmaf(f0.x, shA[kb + 0], shB[kb + 0]), 0.f);
                    ae[1] = fmaxf(fmaf(f0.y, shA[kb + 1], shB[kb + 1]), 0.f);
                    ae[2] = fmaxf(fmaf(f1.x, shA[kb + 2], shB[kb + 2]), 0.f);
                    ae[3] = fmaxf(fmaf(f1.y, shA[kb + 3], shB[kb + 3]), 0.f);
                }
                int k2b = kt * 8;
                #pragma unroll
                for (int u2 = 0; u2 < 4; u2++) {
                    int u = tid + u2 * 256;
                    int k2 = u >> 7, n = u & 127;
                    bs[u2] = Wf[(k2b + k2) * 128 + n];
                }
            };
            auto STOREF = [&](int buf) {
                int m = tid >> 2, kv = (tid & 3) * 4, k2 = kv >> 1;
                __half2 p0 = __floats2half2_rn(ae[0], ae[1]);
                __half2 p1 = __floats2half2_rn(ae[2], ae[3]);
                sAb[buf * 1088 + k2 * SA + m] = *reinterpret_cast<unsigned*>(&p0);
                sAb[buf * 1088 + (k2 + 1) * SA + m] = *reinterpret_cast<unsigned*>(&p1);
                #pragma unroll
                for (int u2 = 0; u2 < 4; u2++) {
                    int u = tid + u2 * 256;
                    int k2u = u >> 7, n = u & 127;
                    sBb[buf * 1088 + k2u * SA + n] = bs[u2];
                }
            };
            auto DOMMA = [&](int buf) {
                int kq = lane & 3;
                unsigned ah[2][4];
                #pragma unroll
                for (int mi = 0; mi < 2; mi++) {
                    int r = wm + mi * 16 + (lane >> 2);
                    ah[mi][0] = sAb[buf * 1088 + kq * SA + r];
                    ah[mi][1] = sAb[buf * 1088 + kq * SA + r + 8];
                    ah[mi][2] = sAb[buf * 1088 + (kq + 4) * SA + r];
                    ah[mi][3] = sAb[buf * 1088 + (kq + 4) * SA + r + 8];
                }
                #pragma unroll
                for (int ni = 0; ni < 4; ni++) {
                    int n = wn + ni * 8 + (lane >> 2);
                    unsigned b0 = sBb[buf * 1088 + kq * SA + n];
                    unsigned b1 = sBb[buf * 1088 + (kq + 4) * SA + n];
                    #pragma unroll
                    for (int mi = 0; mi < 2; mi++)
                        MMA_FP16(acc[mi][ni], ah[mi][0], ah[mi][1], ah[mi][2], ah[mi][3], b0, b1);
                }
            };

            LOADF(0);
            STOREF(0);
            __syncthreads();
            for (int kt = 0; kt < nt; kt++) {
                if (kt + 1 < nt) LOADF(kt + 1);
                DOMMA(kt & 1);
                if (kt + 1 < nt) STOREF((kt + 1) & 1);
                __syncthreads();
            }

            #pragma unroll
            for (int mi = 0; mi < 2; mi++) {
                int r0 = row0 + wm + mi * 16 + (lane >> 2);
                int r1 = r0 + 8;
                float d0 = (r0 < NN) ? g_dinv[r0] : 0.f;
                float d1 = (r1 < NN) ? g_dinv[r1] : 0.f;
                #pragma unroll
                for (int ni = 0; ni < 4; ni++) {
                    int nc = wn + ni * 8 + (lane & 3) * 2;
                    if (r0 < NN)
                        *(__half2*)&g_hs[(size_t)r0 * 128 + nc] =
                            __floats2half2_rn(acc[mi][ni][0] * d0, acc[mi][ni][1] * d0);
                    if (r1 < NN)
                        *(__half2*)&g_hs[(size_t)r1 * 128 + nc] =
                            __floats2half2_rn(acc[mi][ni][2] * d1, acc[mi][ni][3] * d1);
                }
            }
            __syncthreads();
        }
        gsync(++ph, nb);

        // ---- aggregation + BN stats (lane covers halfs [lane*4, lane*4+4)) ----
        if (tid < 128) { shA[tid] = 0.f; shB[tid] = 0.f; }   // sum / sq
        __syncthreads();
        const float* bias = (l == 0) ? b1 : ((l == 1) ? b2 : b3);
        float4 bb = *(const float4*)&bias[lane * 4];
        float4 ss = make_float4(0, 0, 0, 0), qq = make_float4(0, 0, 0, 0);

        for (int grp = bid; grp < NAGG; grp += nb) {
            int i0 = (grp * 8 + warp) * 4;
            #pragma unroll
            for (int tt = 0; tt < 4; tt++) {
                int i = i0 + tt;
                if (i >= NN) break;
                float4 a0 = make_float4(0, 0, 0, 0);
                float4 a1 = make_float4(0, 0, 0, 0);
                float4 a2 = make_float4(0, 0, 0, 0);
                float4 a3 = make_float4(0, 0, 0, 0);
                {
                    uint2 u = __ldcg((const uint2*)&g_hs[(size_t)i * 128 + lane * 4]);
                    float2 f0 = __half22float2(*reinterpret_cast<__half2*>(&u.x));
                    float2 f1 = __half22float2(*reinterpret_cast<__half2*>(&u.y));
                    a0.x += f0.x; a0.y += f0.y; a0.z += f1.x; a0.w += f1.y;
                }
                int s = g_rowptr[i], e = g_rowptr[i + 1];
                int j = s;
                for (; j + 4 <= e; j += 4) {
                    int c0 = g_col[j], c1 = g_col[j + 1], c2 = g_col[j + 2], c3 = g_col[j + 3];
                    uint2 v0 = __ldcg((const uint2*)&g_hs[(size_t)c0 * 128 + lane * 4]);
                    uint2 v1 = __ldcg((const uint2*)&g_hs[(size_t)c1 * 128 + lane * 4]);
                    uint2 v2 = __ldcg((const uint2*)&g_hs[(size_t)c2 * 128 + lane * 4]);
                    uint2 v3 = __ldcg((const uint2*)&g_hs[(size_t)c3 * 128 + lane * 4]);
                    float2 f;
                    f = __half22float2(*reinterpret_cast<__half2*>(&v0.x)); a0.x += f.x; a0.y += f.y;
                    f = __half22float2(*reinterpret_cast<__half2*>(&v0.y)); a0.z += f.x; a0.w += f.y;
                    f = __half22float2(*reinterpret_cast<__half2*>(&v1.x)); a1.x += f.x; a1.y += f.y;
                    f = __half22float2(*reinterpret_cast<__half2*>(&v1.y)); a1.z += f.x; a1.w += f.y;
                    f = __half22float2(*reinterpret_cast<__half2*>(&v2.x)); a2.x += f.x; a2.y += f.y;
                    f = __half22float2(*reinterpret_cast<__half2*>(&v2.y)); a2.z += f.x; a2.w += f.y;
                    f = __half22float2(*reinterpret_cast<__half2*>(&v3.x)); a3.x += f.x; a3.y += f.y;
                    f = __half22float2(*reinterpret_cast<__half2*>(&v3.y)); a3.z += f.x; a3.w += f.y;
                }
                for (; j < e; j++) {
                    int c = g_col[j];
                    uint2 u = __ldcg((const uint2*)&g_hs[(size_t)c * 128 + lane * 4]);
                    float2 f0 = __half22float2(*reinterpret_cast<__half2*>(&u.x));
                    float2 f1 = __half22float2(*reinterpret_cast<__half2*>(&u.y));
                    a0.x += f0.x; a0.y += f0.y; a0.z += f1.x; a0.w += f1.y;
                }
                float di = g_dinv[i];
                float4 o;
                o.x = di * ((a0.x + a1.x) + (a2.x + a3.x)) + bb.x;
                o.y = di * ((a0.y + a1.y) + (a2.y + a3.y)) + bb.y;
                o.z = di * ((a0.z + a1.z) + (a2.z + a3.z)) + bb.z;
                o.w = di * ((a0.w + a1.w) + (a2.w + a3.w)) + bb.w;
                __half2 p0 = __floats2half2_rn(o.x, o.y);
                __half2 p1 = __floats2half2_rn(o.z, o.w);
                uint2 st;
                st.x = *reinterpret_cast<unsigned*>(&p0);
                st.y = *reinterpret_cast<unsigned*>(&p1);
                *(uint2*)&g_agg[(size_t)i * 128 + lane * 4] = st;
                ss.x += o.x; ss.y += o.y; ss.z += o.z; ss.w += o.w;
                qq.x += o.x * o.x; qq.y += o.y * o.y; qq.z += o.z * o.z; qq.w += o.w * o.w;
            }
        }
        int f = lane * 4;
        atomicAdd(&shA[f + 0], ss.x); atomicAdd(&shB[f + 0], qq.x);
        atomicAdd(&shA[f + 1], ss.y); atomicAdd(&shB[f + 1], qq.y);
        atomicAdd(&shA[f + 2], ss.z); atomicAdd(&shB[f + 2], qq.z);
        atomicAdd(&shA[f + 3], ss.w); atomicAdd(&shB[f + 3], qq.w);
        __syncthreads();
        if (tid < 128) {
            atomicAdd(&g_sumA[l][tid], shA[tid]);
            atomicAdd(&g_sqA[l][tid], shB[tid]);
        }
        gsync(++ph, nb);
    }

    // ===== final: pool (BN3+ReLU) + FC head =====
    if (tid < 128) {
        float mean = __ldcg(&g_sumA[2][tid]) * (1.0f / (float)NN);
        float var = __ldcg(&g_sqA[2][tid]) * (1.0f / (float)NN) - mean * mean;
        float a = g3[tid] * rsqrtf(var + BN_EPS);
        shA[tid] = a;
        shB[tid] = be3[tid] - mean * a;
    }
    __syncthreads();
    float* red = (float*)dsm;        // 8 x 128
    float* sp = red + 1024;          // 128
    float* sz = sp + 128;            // 256
    for (int g = bid; g < GG; g += nb) {
        if (tid == 0) {
            int lo = 0, hi = NN;
            while (lo < hi) { int m = (lo + hi) >> 1; if (batch[m] < g) lo = m + 1; else hi = m; }
            s_lo = lo;
            lo = 0; hi = NN;
            while (lo < hi) { int m = (lo + hi) >> 1; if (batch[m] < g + 1) lo = m + 1; else hi = m; }
            s_hi = lo;
        }
        __syncthreads();
        int lo = s_lo, hi = s_hi;
        int f = lane * 4;
        float a0 = shA[f + 0], a1 = shA[f + 1], a2 = shA[f + 2], a3 = shA[f + 3];
        float c0 = shB[f + 0], c1 = shB[f + 1], c2 = shB[f + 2], c3 = shB[f + 3];
        float4 pacc[4];
        #pragma unroll
        for (int u = 0; u < 4; u++) pacc[u] = make_float4(0, 0, 0, 0);
        for (int base = lo + warp; base < hi; base += 32) {
            #pragma unroll
            for (int u = 0; u < 4; u++) {
                int i = base + u * 8;
                if (i < hi) {
                    uint2 v = __ldcg((const uint2*)&g_agg[(size_t)i * 128 + lane * 4]);
                    float2 x0 = __half22float2(*reinterpret_cast<__half2*>(&v.x));
                    float2 x1 = __half22float2(*reinterpret_cast<__half2*>(&v.y));
                    pacc[u].x += fmaxf(fmaf(x0.x, a0, c0), 0.f);
                    pacc[u].y += fmaxf(fmaf(x0.y, a1, c1), 0.f);
                    pacc[u].z += fmaxf(fmaf(x1.x, a2, c2), 0.f);
                    pacc[u].w += fmaxf(fmaf(x1.y, a3, c3), 0.f);
                }
            }
        }
        red[warp * 128 + f + 0] = (pacc[0].x + pacc[1].x) + (pacc[2].x + pacc[3].x);
        red[warp * 128 + f + 1] = (pacc[0].y + pacc[1].y) + (pacc[2].y + pacc[3].y);
        red[warp * 128 + f + 2] = (pacc[0].z + pacc[1].z) + (pacc[2].z + pacc[3].z);
        red[warp * 128 + f + 3] = (pacc[0].w + pacc[1].w) + (pacc[2].w + pacc[3].w);
        __syncthreads();
        if (tid < 128) {
            float s = 0.f;
            #pragma unroll
            for (int w = 0; w < 8; w++) s += red[w * 128 + tid];
            float cnt = fmaxf((float)(hi - lo), 1.0f);
            sp[tid] = s / cnt;
        }
        __syncthreads();
        float accf = bf1[tid];
        #pragma unroll 8
        for (int k = 0; k < 128; k++) accf = fmaf(sp[k], Wf1[k * 256 + tid], accf);
        sz[tid] = fmaxf(accf, 0.f);
        __syncthreads();
        if (tid < 10) {
            float o = bf2[tid];
            #pragma unroll 8
            for (int k = 0; k < 256; k++) o = fmaf(sz[k], Wf2[k * 10 + tid], o);
            out[g * 10 + tid] = o;
        }
        __syncthreads();
    }
}

// ---------------- launch ------------------------------------------------------
extern "C" void kernel_launch(void* const* d_in, const int* in_sizes, int n_in,
                              void* d_out, int out_size) {
    const float* x     = (const float*)d_in[0];
    const int*   ei    = (const int*)d_in[1];
    const int*   batch = (const int*)d_in[2];
    const float* W1 = (const float*)d_in[3];
    const float* b1 = (const float*)d_in[4];
    const float* g1 = (const float*)d_in[5];
    const float* be1 = (const float*)d_in[6];
    const float* W2 = (const float*)d_in[7];
    const float* b2 = (const float*)d_in[8];
    const float* g2 = (const float*)d_in[9];
    const float* be2 = (const float*)d_in[10];
    const float* W3 = (const float*)d_in[11];
    const float* b3 = (const float*)d_in[12];
    const float* g3 = (const float*)d_in[13];
    const float* be3 = (const float*)d_in[14];
    const float* Wf1 = (const float*)d_in[15];
    const float* bf1 = (const float*)d_in[16];
    const float* Wf2 = (const float*)d_in[17];
    const float* bf2 = (const float*)d_in[18];
    float* out = (float*)d_out;

    const int* src = ei;
    const int* dst = ei + EE;

    static int nb_cached = 0;
    if (!nb_cached) {
        int dev = 0, sms = 0, bpm = 0;
        cudaGetDevice(&dev);
        cudaDeviceGetAttribute(&sms, cudaDevAttrMultiProcessorCount, dev);
        cudaOccupancyMaxActiveBlocksPerMultiprocessor(&bpm, k_fused, 256, DSM_BYTES);
        if (bpm < 1) bpm = 1;
        long nb = (long)sms * bpm;
        if (nb > 2048) nb = 2048;
        nb_cached = (int)nb;
    }

    k_init<<<88, 256>>>(W1, W2, W3);
    k_fused<<<nb_cached, 256, DSM_BYTES>>>(
        x, src, dst, batch, b1, b2, b3,
        g1, be1, g2, be2, g3, be3,
        Wf1, bf1, Wf2, bf2, out);
}

// round 13
// speedup vs baseline: 1.9391x; 1.1340x over previous
#include <cuda_runtime.h>
#include <cuda_fp16.h>
#include <cstdint>

#define NN 50000
#define EE 800000
#define GG 64
#define BN_EPS 1e-5f
#define NTILE 782          // ceil(NN/64)
#define NAGG 1563          // ceil(NN/32)
#define SA 136             // smem stride (conflict-free)
#define DSM_BYTES 17408    // 4352 uints: 2-buf A (2176) + 2-buf B (2176)

// ---------------- device globals (no allocation) -----------------------------
__device__ __half g_hs[(size_t)NN * 128];   // GEMM out (dinv-scaled) fp16
__device__ __half g_agg[(size_t)NN * 128];  // aggregated (pre-BN) fp16
__device__ float g_dinv[NN];
__device__ int   g_deg[NN];                 // zero at load; re-zeroed each run
__device__ int   g_rowptr[NN + 1];
__device__ int   g_cursor[NN];
__device__ int   g_col[EE];
__device__ float g_sumA[3][128], g_sqA[3][128];
__device__ unsigned g_wf[3][64 * 128];      // packed half2 weights
__device__ int   g_bsum[2048], g_bsum2[2048];
__device__ unsigned g_barcnt;
__device__ volatile unsigned g_release;

// ---------------- init: reset barrier + stats, pack W ------------------------
__global__ void k_init(const float* __restrict__ W1, const float* __restrict__ W2,
                       const float* __restrict__ W3) {
    int i = blockIdx.x * blockDim.x + threadIdx.x;
    if (i == 0) { g_barcnt = 0; g_release = 0; }
    if (i < 128) {
        #pragma unroll
        for (int l = 0; l < 3; l++) { g_sumA[l][i] = 0.f; g_sqA[l][i] = 0.f; }
    }
    int l = -1, idx = 0;
    const float* W = nullptr;
    if (i < 6144) { l = 0; idx = i; W = W1; }
    else if (i < 6144 + 8192) { l = 1; idx = i - 6144; W = W2; }
    else if (i < 6144 + 16384) { l = 2; idx = i - 14336; W = W3; }
    if (l >= 0) {
        int k2 = idx >> 7, n = idx & 127;
        float w0 = W[(size_t)(2 * k2) * 128 + n];
        float w1 = W[(size_t)(2 * k2 + 1) * 128 + n];
        __half2 p = __floats2half2_rn(w0, w1);
        g_wf[l][idx] = *reinterpret_cast<unsigned*>(&p);
    }
}

// ---------------- grid barrier (all blocks resident) -------------------------
__device__ __forceinline__ void gsync(int phase, int nb) {
    __threadfence();
    __syncthreads();
    if (threadIdx.x == 0) {
        unsigned target = (unsigned)phase * (unsigned)nb;
        unsigned old = atomicAdd(&g_barcnt, 1u);
        if (old + 1u == target) {
            g_release = (unsigned)phase;
            __threadfence();
        } else {
            while (g_release < (unsigned)phase) __nanosleep(64);
            __threadfence();
        }
    }
    __syncthreads();
}

#define MMA_FP16(C, a0, a1, a2, a3, b0, b1)                                        \
    asm volatile(                                                                  \
        "mma.sync.aligned.m16n8k16.row.col.f32.f16.f16.f32 "                       \
        "{%0,%1,%2,%3},{%4,%5,%6,%7},{%8,%9},{%0,%1,%2,%3};"                       \
        : "+f"((C)[0]), "+f"((C)[1]), "+f"((C)[2]), "+f"((C)[3])                   \
        : "r"(a0), "r"(a1), "r"(a2), "r"(a3), "r"(b0), "r"(b1))

// ---------------- GEMM tile phase (shared by fork & layer loop) --------------
// L0=1: A = x (fp32, no BN). L0=0: A = g_agg (fp16, BN+ReLU via shA/shB).
template <int L0>
__device__ __forceinline__ void gemm_phase(
    const float* __restrict__ x, const unsigned* __restrict__ Wf,
    int K, int nt, int tstart, int tstride, unsigned* dsm,
    const float* shA, const float* shB, int tid, int lane, int warp) {
    unsigned* sAb = dsm;          // 2 x 1088
    unsigned* sBb = dsm + 2176;   // 2 x 1088
    int wm = (warp >> 2) * 32;
    int wn = (warp & 3) * 32;
    for (int t = tstart; t < NTILE; t += tstride) {
        int row0 = t * 64;
        float acc[2][4][4];
        #pragma unroll
        for (int mi = 0; mi < 2; mi++)
            #pragma unroll
            for (int ni = 0; ni < 4; ni++)
                #pragma unroll
                for (int q = 0; q < 4; q++) acc[mi][ni][q] = 0.f;

        float ae[4];
        unsigned bs[4];

        auto LOADF = [&](int kt) {
            int k0 = kt * 16;
            int m = tid >> 2, kv = (tid & 3) * 4, gm = row0 + m;
            if (L0) {
                float4 v = make_float4(0.f, 0.f, 0.f, 0.f);
                if (gm < NN) v = *(const float4*)&x[(size_t)gm * 96 + k0 + kv];
                ae[0] = v.x; ae[1] = v.y; ae[2] = v.z; ae[3] = v.w;
            } else {
                uint2 hv = make_uint2(0u, 0u);
                if (gm < NN) hv = __ldcg((const uint2*)&g_agg[(size_t)gm * 128 + k0 + kv]);
                float2 f0 = __half22float2(*reinterpret_cast<__half2*>(&hv.x));
                float2 f1 = __half22float2(*reinterpret_cast<__half2*>(&hv.y));
                int kb = k0 + kv;
                ae[0] = fmaxf(fmaf(f0.x, shA[kb + 0], shB[kb + 0]), 0.f);
                ae[1] = fmaxf(fmaf(f0.y, shA[kb + 1], shB[kb + 1]), 0.f);
                ae[2] = fmaxf(fmaf(f1.x, shA[kb + 2], shB[kb + 2]), 0.f);
                ae[3] = fmaxf(fmaf(f1.y, shA[kb + 3], shB[kb + 3]), 0.f);
            }
            int k2b = kt * 8;
            #pragma unroll
            for (int u2 = 0; u2 < 4; u2++) {
                int u = tid + u2 * 256;
                int k2 = u >> 7, n = u & 127;
                bs[u2] = Wf[(k2b + k2) * 128 + n];
            }
        };
        auto STOREF = [&](int buf) {
            int m = tid >> 2, kv = (tid & 3) * 4, k2 = kv >> 1;
            __half2 p0 = __floats2half2_rn(ae[0], ae[1]);
            __half2 p1 = __floats2half2_rn(ae[2], ae[3]);
            sAb[buf * 1088 + k2 * SA + m] = *reinterpret_cast<unsigned*>(&p0);
            sAb[buf * 1088 + (k2 + 1) * SA + m] = *reinterpret_cast<unsigned*>(&p1);
            #pragma unroll
            for (int u2 = 0; u2 < 4; u2++) {
                int u = tid + u2 * 256;
                int k2u = u >> 7, n = u & 127;
                sBb[buf * 1088 + k2u * SA + n] = bs[u2];
            }
        };
        auto DOMMA = [&](int buf) {
            int kq = lane & 3;
            unsigned ah[2][4];
            #pragma unroll
            for (int mi = 0; mi < 2; mi++) {
                int r = wm + mi * 16 + (lane >> 2);
                ah[mi][0] = sAb[buf * 1088 + kq * SA + r];
                ah[mi][1] = sAb[buf * 1088 + kq * SA + r + 8];
                ah[mi][2] = sAb[buf * 1088 + (kq + 4) * SA + r];
                ah[mi][3] = sAb[buf * 1088 + (kq + 4) * SA + r + 8];
            }
            #pragma unroll
            for (int ni = 0; ni < 4; ni++) {
                int n = wn + ni * 8 + (lane >> 2);
                unsigned b0 = sBb[buf * 1088 + kq * SA + n];
                unsigned b1 = sBb[buf * 1088 + (kq + 4) * SA + n];
                #pragma unroll
                for (int mi = 0; mi < 2; mi++)
                    MMA_FP16(acc[mi][ni], ah[mi][0], ah[mi][1], ah[mi][2], ah[mi][3], b0, b1);
            }
        };

        LOADF(0);
        STOREF(0);
        __syncthreads();
        for (int kt = 0; kt < nt; kt++) {
            if (kt + 1 < nt) LOADF(kt + 1);
            DOMMA(kt & 1);
            if (kt + 1 < nt) STOREF((kt + 1) & 1);
            __syncthreads();
        }

        #pragma unroll
        for (int mi = 0; mi < 2; mi++) {
            int r0 = row0 + wm + mi * 16 + (lane >> 2);
            int r1 = r0 + 8;
            float d0 = (r0 < NN) ? g_dinv[r0] : 0.f;
            float d1 = (r1 < NN) ? g_dinv[r1] : 0.f;
            #pragma unroll
            for (int ni = 0; ni < 4; ni++) {
                int nc = wn + ni * 8 + (lane & 3) * 2;
                if (r0 < NN)
                    *(__half2*)&g_hs[(size_t)r0 * 128 + nc] =
                        __floats2half2_rn(acc[mi][ni][0] * d0, acc[mi][ni][1] * d0);
                if (r1 < NN)
                    *(__half2*)&g_hs[(size_t)r1 * 128 + nc] =
                        __floats2half2_rn(acc[mi][ni][2] * d1, acc[mi][ni][3] * d1);
            }
        }
        __syncthreads();
    }
}

// ---------------- the fused persistent kernel --------------------------------
__global__ __launch_bounds__(256, 3) void k_fused(
    const float* __restrict__ x,
    const int* __restrict__ src, const int* __restrict__ dst,
    const int* __restrict__ batch,
    const float* __restrict__ b1, const float* __restrict__ b2, const float* __restrict__ b3,
    const float* __restrict__ g1, const float* __restrict__ be1,
    const float* __restrict__ g2, const float* __restrict__ be2,
    const float* __restrict__ g3, const float* __restrict__ be3,
    const float* __restrict__ Wf1, const float* __restrict__ bf1,
    const float* __restrict__ Wf2, const float* __restrict__ bf2,
    float* __restrict__ out) {
    extern __shared__ unsigned dsm[];
    __shared__ float shA[128], shB[128];
    __shared__ int s_lo, s_hi;

    const int nb = gridDim.x;
    const int bid = blockIdx.x;
    const int tid = threadIdx.x, lane = tid & 31, warp = tid >> 5;
    int ph = 0;

    // ===== P0: degree count =====
    for (int e = bid * 256 + tid; e < EE; e += nb * 256)
        atomicAdd(&g_deg[dst[e]], 1);
    gsync(++ph, nb);

    // ===== P1: per-block partial sums of deg =====
    const int chunk = (NN + nb - 1) / nb;
    const int start = bid * chunk;
    const int end = (start + chunk < NN) ? start + chunk : NN;
    {
        int* part = (int*)dsm;
        int s = 0;
        for (int i = start + tid; i < end; i += 256) s += __ldcg(&g_deg[i]);
        part[tid] = s;
        __syncthreads();
        for (int off = 128; off; off >>= 1) {
            if (tid < off) part[tid] += part[tid + off];
            __syncthreads();
        }
        if (tid == 0) g_bsum[bid] = part[0];
    }
    gsync(++ph, nb);

    // ===== P2: block 0 exclusive-scans block sums =====
    if (bid == 0) {
        int* part = (int*)dsm;
        int CH2 = (nb + 255) / 256;
        int s = 0;
        for (int j = 0; j < CH2; j++) {
            int idx = tid * CH2 + j;
            if (idx < nb) s += __ldcg(&g_bsum[idx]);
        }
        part[tid] = s;
        __syncthreads();
        int own = s;
        for (int off = 1; off < 256; off <<= 1) {
            int v = 0;
            if (tid >= off) v = part[tid - off];
            __syncthreads();
            if (tid >= off) part[tid] += v;
            __syncthreads();
        }
        int run = part[tid] - own;
        for (int j = 0; j < CH2; j++) {
            int idx = tid * CH2 + j;
            if (idx < nb) { g_bsum2[idx] = run; run += __ldcg(&g_bsum[idx]); }
        }
    }
    gsync(++ph, nb);

    // ===== P3: finalize rowptr/cursor/dinv, re-zero deg =====
    {
        int* part = (int*)dsm;
        int base = __ldcg(&g_bsum2[bid]);
        int CHL = (chunk + 255) / 256;
        int s = 0;
        for (int j = 0; j < CHL; j++) {
            int i = start + tid * CHL + j;
            if (i < end) s += __ldcg(&g_deg[i]);
        }
        part[tid] = s;
        __syncthreads();
        int own = s;
        for (int off = 1; off < 256; off <<= 1) {
            int v = 0;
            if (tid >= off) v = part[tid - off];
            __syncthreads();
            if (tid >= off) part[tid] += v;
            __syncthreads();
        }
        int run = base + part[tid] - own;
        for (int j = 0; j < CHL; j++) {
            int i = start + tid * CHL + j;
            if (i < end) {
                int d = __ldcg(&g_deg[i]);
                g_cursor[i] = run;
                run += d;
                g_rowptr[i + 1] = run;
                g_dinv[i] = rsqrtf((float)d + 1.0f);
                g_deg[i] = 0;
            }
        }
        if (bid == 0 && tid == 0) g_rowptr[0] = 0;
    }
    gsync(++ph, nb);

    // ===== P4 FORK: team P fills CSR || team G runs GEMM layer 1 =====
    {
        int nbP = nb / 3;
        if (nbP < 1) nbP = 1;
        if (bid < nbP) {
            for (int e = bid * 256 + tid; e < EE; e += nbP * 256) {
                int d = dst[e];
                int p = atomicAdd(&g_cursor[d], 1);
                g_col[p] = src[e];
            }
        } else {
            gemm_phase<1>(x, g_wf[0], 96, 6, bid - nbP, nb - nbP, dsm,
                          shA, shB, tid, lane, warp);
        }
    }
    gsync(++ph, nb);

    // ===== layers: (GEMM for l>=1) -> aggregate =====
    for (int l = 0; l < 3; l++) {
        if (l > 0) {
            // BN coefficients for this layer's input
            if (tid < 128) {
                float mean = __ldcg(&g_sumA[l - 1][tid]) * (1.0f / (float)NN);
                float var = __ldcg(&g_sqA[l - 1][tid]) * (1.0f / (float)NN) - mean * mean;
                const float* gm = (l == 1) ? g1 : g2;
                const float* bt = (l == 1) ? be1 : be2;
                float a = gm[tid] * rsqrtf(var + BN_EPS);
                shA[tid] = a;
                shB[tid] = bt[tid] - mean * a;
            }
            __syncthreads();
            gemm_phase<0>(x, g_wf[l], 128, 8, bid, nb, dsm, shA, shB, tid, lane, warp);
            gsync(++ph, nb);
        }

        // ---- aggregation + BN stats (lane covers halfs [lane*4, lane*4+4)) ----
        if (tid < 128) { shA[tid] = 0.f; shB[tid] = 0.f; }   // sum / sq
        __syncthreads();
        const float* bias = (l == 0) ? b1 : ((l == 1) ? b2 : b3);
        float4 bb = *(const float4*)&bias[lane * 4];
        float4 ss = make_float4(0, 0, 0, 0), qq = make_float4(0, 0, 0, 0);

        for (int grp = bid; grp < NAGG; grp += nb) {
            int i0 = (grp * 8 + warp) * 4;
            #pragma unroll
            for (int tt = 0; tt < 4; tt++) {
                int i = i0 + tt;
                if (i >= NN) break;
                float4 a0 = make_float4(0, 0, 0, 0);
                float4 a1 = make_float4(0, 0, 0, 0);
                float4 a2 = make_float4(0, 0, 0, 0);
                float4 a3 = make_float4(0, 0, 0, 0);
                {
                    uint2 u = __ldcg((const uint2*)&g_hs[(size_t)i * 128 + lane * 4]);
                    float2 f0 = __half22float2(*reinterpret_cast<__half2*>(&u.x));
                    float2 f1 = __half22float2(*reinterpret_cast<__half2*>(&u.y));
                    a0.x += f0.x; a0.y += f0.y; a0.z += f1.x; a0.w += f1.y;
                }
                int s = g_rowptr[i], e = g_rowptr[i + 1];
                int j = s;
                for (; j + 4 <= e; j += 4) {
                    int c0 = g_col[j], c1 = g_col[j + 1], c2 = g_col[j + 2], c3 = g_col[j + 3];
                    uint2 v0 = __ldcg((const uint2*)&g_hs[(size_t)c0 * 128 + lane * 4]);
                    uint2 v1 = __ldcg((const uint2*)&g_hs[(size_t)c1 * 128 + lane * 4]);
                    uint2 v2 = __ldcg((const uint2*)&g_hs[(size_t)c2 * 128 + lane * 4]);
                    uint2 v3 = __ldcg((const uint2*)&g_hs[(size_t)c3 * 128 + lane * 4]);
                    float2 f;
                    f = __half22float2(*reinterpret_cast<__half2*>(&v0.x)); a0.x += f.x; a0.y += f.y;
                    f = __half22float2(*reinterpret_cast<__half2*>(&v0.y)); a0.z += f.x; a0.w += f.y;
                    f = __half22float2(*reinterpret_cast<__half2*>(&v1.x)); a1.x += f.x; a1.y += f.y;
                    f = __half22float2(*reinterpret_cast<__half2*>(&v1.y)); a1.z += f.x; a1.w += f.y;
                    f = __half22float2(*reinterpret_cast<__half2*>(&v2.x)); a2.x += f.x; a2.y += f.y;
                    f = __half22float2(*reinterpret_cast<__half2*>(&v2.y)); a2.z += f.x; a2.w += f.y;
                    f = __half22float2(*reinterpret_cast<__half2*>(&v3.x)); a3.x += f.x; a3.y += f.y;
                    f = __half22float2(*reinterpret_cast<__half2*>(&v3.y)); a3.z += f.x; a3.w += f.y;
                }
                for (; j < e; j++) {
                    int c = g_col[j];
                    uint2 u = __ldcg((const uint2*)&g_hs[(size_t)c * 128 + lane * 4]);
                    float2 f0 = __half22float2(*reinterpret_cast<__half2*>(&u.x));
                    float2 f1 = __half22float2(*reinterpret_cast<__half2*>(&u.y));
                    a0.x += f0.x; a0.y += f0.y; a0.z += f1.x; a0.w += f1.y;
                }
                float di = g_dinv[i];
                float4 o;
                o.x = di * ((a0.x + a1.x) + (a2.x + a3.x)) + bb.x;
                o.y = di * ((a0.y + a1.y) + (a2.y + a3.y)) + bb.y;
                o.z = di * ((a0.z + a1.z) + (a2.z + a3.z)) + bb.z;
                o.w = di * ((a0.w + a1.w) + (a2.w + a3.w)) + bb.w;
                __half2 p0 = __floats2half2_rn(o.x, o.y);
                __half2 p1 = __floats2half2_rn(o.z, o.w);
                uint2 st;
                st.x = *reinterpret_cast<unsigned*>(&p0);
                st.y = *reinterpret_cast<unsigned*>(&p1);
                *(uint2*)&g_agg[(size_t)i * 128 + lane * 4] = st;
                ss.x += o.x; ss.y += o.y; ss.z += o.z; ss.w += o.w;
                qq.x += o.x * o.x; qq.y += o.y * o.y; qq.z += o.z * o.z; qq.w += o.w * o.w;
            }
        }
        int f = lane * 4;
        atomicAdd(&shA[f + 0], ss.x); atomicAdd(&shB[f + 0], qq.x);
        atomicAdd(&shA[f + 1], ss.y); atomicAdd(&shB[f + 1], qq.y);
        atomicAdd(&shA[f + 2], ss.z); atomicAdd(&shB[f + 2], qq.z);
        atomicAdd(&shA[f + 3], ss.w); atomicAdd(&shB[f + 3], qq.w);
        __syncthreads();
        if (tid < 128) {
            atomicAdd(&g_sumA[l][tid], shA[tid]);
            atomicAdd(&g_sqA[l][tid], shB[tid]);
        }
        gsync(++ph, nb);
    }

    // ===== final: pool (BN3+ReLU) + FC head =====
    if (tid < 128) {
        float mean = __ldcg(&g_sumA[2][tid]) * (1.0f / (float)NN);
        float var = __ldcg(&g_sqA[2][tid]) * (1.0f / (float)NN) - mean * mean;
        float a = g3[tid] * rsqrtf(var + BN_EPS);
        shA[tid] = a;
        shB[tid] = be3[tid] - mean * a;
    }
    __syncthreads();
    float* red = (float*)dsm;        // 8 x 128
    float* sp = red + 1024;          // 128
    float* sz = sp + 128;            // 256
    for (int g = bid; g < GG; g += nb) {
        if (tid == 0) {
            int lo = 0, hi = NN;
            while (lo < hi) { int m = (lo + hi) >> 1; if (batch[m] < g) lo = m + 1; else hi = m; }
            s_lo = lo;
            lo = 0; hi = NN;
            while (lo < hi) { int m = (lo + hi) >> 1; if (batch[m] < g + 1) lo = m + 1; else hi = m; }
            s_hi = lo;
        }
        __syncthreads();
        int lo = s_lo, hi = s_hi;
        int f = lane * 4;
        float a0 = shA[f + 0], a1 = shA[f + 1], a2 = shA[f + 2], a3 = shA[f + 3];
        float c0 = shB[f + 0], c1 = shB[f + 1], c2 = shB[f + 2], c3 = shB[f + 3];
        float4 pacc[4];
        #pragma unroll
        for (int u = 0; u < 4; u++) pacc[u] = make_float4(0, 0, 0, 0);
        for (int base = lo + warp; base < hi; base += 32) {
            #pragma unroll
            for (int u = 0; u < 4; u++) {
                int i = base + u * 8;
                if (i < hi) {
                    uint2 v = __ldcg((const uint2*)&g_agg[(size_t)i * 128 + lane * 4]);
                    float2 x0 = __half22float2(*reinterpret_cast<__half2*>(&v.x));
                    float2 x1 = __half22float2(*reinterpret_cast<__half2*>(&v.y));
                    pacc[u].x += fmaxf(fmaf(x0.x, a0, c0), 0.f);
                    pacc[u].y += fmaxf(fmaf(x0.y, a1, c1), 0.f);
                    pacc[u].z += fmaxf(fmaf(x1.x, a2, c2), 0.f);
                    pacc[u].w += fmaxf(fmaf(x1.y, a3, c3), 0.f);
                }
            }
        }
        red[warp * 128 + f + 0] = (pacc[0].x + pacc[1].x) + (pacc[2].x + pacc[3].x);
        red[warp * 128 + f + 1] = (pacc[0].y + pacc[1].y) + (pacc[2].y + pacc[3].y);
        red[warp * 128 + f + 2] = (pacc[0].z + pacc[1].z) + (pacc[2].z + pacc[3].z);
        red[warp * 128 + f + 3] = (pacc[0].w + pacc[1].w) + (pacc[2].w + pacc[3].w);
        __syncthreads();
        if (tid < 128) {
            float s = 0.f;
            #pragma unroll
            for (int w = 0; w < 8; w++) s += red[w * 128 + tid];
            float cnt = fmaxf((float)(hi - lo), 1.0f);
            sp[tid] = s / cnt;
        }
        __syncthreads();
        float accf = bf1[tid];
        #pragma unroll 8
        for (int k = 0; k < 128; k++) accf = fmaf(sp[k], Wf1[k * 256 + tid], accf);
        sz[tid] = fmaxf(accf, 0.f);
        __syncthreads();
        if (tid < 10) {
            float o = bf2[tid];
            #pragma unroll 8
            for (int k = 0; k < 256; k++) o = fmaf(sz[k], Wf2[k * 10 + tid], o);
            out[g * 10 + tid] = o;
        }
        __syncthreads();
    }
}

// ---------------- launch ------------------------------------------------------
extern "C" void kernel_launch(void* const* d_in, const int* in_sizes, int n_in,
                              void* d_out, int out_size) {
    const float* x     = (const float*)d_in[0];
    const int*   ei    = (const int*)d_in[1];
    const int*   batch = (const int*)d_in[2];
    const float* W1 = (const float*)d_in[3];
    const float* b1 = (const float*)d_in[4];
    const float* g1 = (const float*)d_in[5];
    const float* be1 = (const float*)d_in[6];
    const float* W2 = (const float*)d_in[7];
    const float* b2 = (const float*)d_in[8];
    const float* g2 = (const float*)d_in[9];
    const float* be2 = (const float*)d_in[10];
    const float* W3 = (const float*)d_in[11];
    const float* b3 = (const float*)d_in[12];
    const float* g3 = (const float*)d_in[13];
    const float* be3 = (const float*)d_in[14];
    const float* Wf1 = (const float*)d_in[15];
    const float* bf1 = (const float*)d_in[16];
    const float* Wf2 = (const float*)d_in[17];
    const float* bf2 = (const float*)d_in[18];
    float* out = (float*)d_out;

    const int* src = ei;
    const int* dst = ei + EE;

    static int nb_cached = 0;
    if (!nb_cached) {
        int dev = 0, sms = 0, bpm = 0;
        cudaGetDevice(&dev);
        cudaDeviceGetAttribute(&sms, cudaDevAttrMultiProcessorCount, dev);
        cudaOccupancyMaxActiveBlocksPerMultiprocessor(&bpm, k_fused, 256, DSM_BYTES);
        if (bpm < 1) bpm = 1;
        long nb = (long)sms * bpm;
        if (nb > 2048) nb = 2048;
        nb_cached = (int)nb;
    }

    k_init<<<88, 256>>>(W1, W2, W3);
    k_fused<<<nb_cached, 256, DSM_BYTES>>>(
        x, src, dst, batch, b1, b2, b3,
        g1, be1, g2, be2, g3, be3,
        Wf1, bf1, Wf2, bf2, out);
}

// round 14
// speedup vs baseline: 2.1060x; 1.0860x over previous
#include <cuda_runtime.h>
#include <cuda_fp16.h>
#include <cstdint>

#define NN 50000
#define EE 800000
#define GG 64
#define BN_EPS 1e-5f
#define NTILE 782          // ceil(NN/64)
#define NAGG 1563          // ceil(NN/32)
#define SA 136             // smem stride (conflict-free)
#define DSM_BYTES 17408    // 4352 uints: 2-buf A (2176) + 2-buf B (2176)

// ---------------- device globals (no allocation) -----------------------------
__device__ __half g_hs[(size_t)NN * 128];   // GEMM out (dinv-scaled) fp16
__device__ __half g_agg[(size_t)NN * 128];  // aggregated (pre-BN) fp16
__device__ float g_dinv[NN];
__device__ int   g_deg[NN];                 // zero at load; re-zeroed each run
__device__ int   g_rowptr[NN + 1];
__device__ int   g_cursor[NN];
__device__ int   g_col[EE];
__device__ float g_sumA[3][128], g_sqA[3][128];
__device__ unsigned g_wf[3][64 * 128];      // packed half2 weights
__device__ int   g_bsum[2048], g_bsum2[2048];
__device__ unsigned g_barcnt;
__device__ volatile unsigned g_release;

// ---------------- init: reset barrier + stats, pack W ------------------------
__global__ void k_init(const float* __restrict__ W1, const float* __restrict__ W2,
                       const float* __restrict__ W3) {
    int i = blockIdx.x * blockDim.x + threadIdx.x;
    if (i == 0) { g_barcnt = 0; g_release = 0; }
    if (i < 128) {
        #pragma unroll
        for (int l = 0; l < 3; l++) { g_sumA[l][i] = 0.f; g_sqA[l][i] = 0.f; }
    }
    int l = -1, idx = 0;
    const float* W = nullptr;
    if (i < 6144) { l = 0; idx = i; W = W1; }
    else if (i < 6144 + 8192) { l = 1; idx = i - 6144; W = W2; }
    else if (i < 6144 + 16384) { l = 2; idx = i - 14336; W = W3; }
    if (l >= 0) {
        int k2 = idx >> 7, n = idx & 127;
        float w0 = W[(size_t)(2 * k2) * 128 + n];
        float w1 = W[(size_t)(2 * k2 + 1) * 128 + n];
        __half2 p = __floats2half2_rn(w0, w1);
        g_wf[l][idx] = *reinterpret_cast<unsigned*>(&p);
    }
}

// ---------------- grid barrier (all blocks resident) -------------------------
__device__ __forceinline__ void gsync(int phase, int nb) {
    __threadfence();
    __syncthreads();
    if (threadIdx.x == 0) {
        unsigned target = (unsigned)phase * (unsigned)nb;
        unsigned old = atomicAdd(&g_barcnt, 1u);
        if (old + 1u == target) {
            g_release = (unsigned)phase;
            __threadfence();
        } else {
            while (g_release < (unsigned)phase) __nanosleep(64);
            __threadfence();
        }
    }
    __syncthreads();
}

#define MMA_FP16(C, a0, a1, a2, a3, b0, b1)                                        \
    asm volatile(                                                                  \
        "mma.sync.aligned.m16n8k16.row.col.f32.f16.f16.f32 "                       \
        "{%0,%1,%2,%3},{%4,%5,%6,%7},{%8,%9},{%0,%1,%2,%3};"                       \
        : "+f"((C)[0]), "+f"((C)[1]), "+f"((C)[2]), "+f"((C)[3])                   \
        : "r"(a0), "r"(a1), "r"(a2), "r"(a3), "r"(b0), "r"(b1))

// unpack uint4 (8 halfs) and add into 8 fp32 accumulators
__device__ __forceinline__ void acc8(float* a, uint4 u) {
    float2 f;
    f = __half22float2(*reinterpret_cast<__half2*>(&u.x)); a[0] += f.x; a[1] += f.y;
    f = __half22float2(*reinterpret_cast<__half2*>(&u.y)); a[2] += f.x; a[3] += f.y;
    f = __half22float2(*reinterpret_cast<__half2*>(&u.z)); a[4] += f.x; a[5] += f.y;
    f = __half22float2(*reinterpret_cast<__half2*>(&u.w)); a[6] += f.x; a[7] += f.y;
}

// ---------------- GEMM tile phase (shared by fork & layer loop) --------------
// L0=1: A = x (fp32, no BN). L0=0: A = g_agg (fp16, BN+ReLU via shA/shB).
template <int L0>
__device__ __forceinline__ void gemm_phase(
    const float* __restrict__ x, const unsigned* __restrict__ Wf,
    int K, int nt, int tstart, int tstride, unsigned* dsm,
    const float* shA, const float* shB, int tid, int lane, int warp) {
    unsigned* sAb = dsm;          // 2 x 1088
    unsigned* sBb = dsm + 2176;   // 2 x 1088
    int wm = (warp >> 2) * 32;
    int wn = (warp & 3) * 32;
    for (int t = tstart; t < NTILE; t += tstride) {
        int row0 = t * 64;
        float acc[2][4][4];
        #pragma unroll
        for (int mi = 0; mi < 2; mi++)
            #pragma unroll
            for (int ni = 0; ni < 4; ni++)
                #pragma unroll
                for (int q = 0; q < 4; q++) acc[mi][ni][q] = 0.f;

        float ae[4];
        unsigned bs[4];

        auto LOADF = [&](int kt) {
            int k0 = kt * 16;
            int m = tid >> 2, kv = (tid & 3) * 4, gm = row0 + m;
            if (L0) {
                float4 v = make_float4(0.f, 0.f, 0.f, 0.f);
                if (gm < NN) v = *(const float4*)&x[(size_t)gm * 96 + k0 + kv];
                ae[0] = v.x; ae[1] = v.y; ae[2] = v.z; ae[3] = v.w;
            } else {
                uint2 hv = make_uint2(0u, 0u);
                if (gm < NN) hv = __ldcg((const uint2*)&g_agg[(size_t)gm * 128 + k0 + kv]);
                float2 f0 = __half22float2(*reinterpret_cast<__half2*>(&hv.x));
                float2 f1 = __half22float2(*reinterpret_cast<__half2*>(&hv.y));
                int kb = k0 + kv;
                ae[0] = fmaxf(fmaf(f0.x, shA[kb + 0], shB[kb + 0]), 0.f);
                ae[1] = fmaxf(fmaf(f0.y, shA[kb + 1], shB[kb + 1]), 0.f);
                ae[2] = fmaxf(fmaf(f1.x, shA[kb + 2], shB[kb + 2]), 0.f);
                ae[3] = fmaxf(fmaf(f1.y, shA[kb + 3], shB[kb + 3]), 0.f);
            }
            int k2b = kt * 8;
            #pragma unroll
            for (int u2 = 0; u2 < 4; u2++) {
                int u = tid + u2 * 256;
                int k2 = u >> 7, n = u & 127;
                bs[u2] = Wf[(k2b + k2) * 128 + n];
            }
        };
        auto STOREF = [&](int buf) {
            int m = tid >> 2, kv = (tid & 3) * 4, k2 = kv >> 1;
            __half2 p0 = __floats2half2_rn(ae[0], ae[1]);
            __half2 p1 = __floats2half2_rn(ae[2], ae[3]);
            sAb[buf * 1088 + k2 * SA + m] = *reinterpret_cast<unsigned*>(&p0);
            sAb[buf * 1088 + (k2 + 1) * SA + m] = *reinterpret_cast<unsigned*>(&p1);
            #pragma unroll
            for (int u2 = 0; u2 < 4; u2++) {
                int u = tid + u2 * 256;
                int k2u = u >> 7, n = u & 127;
                sBb[buf * 1088 + k2u * SA + n] = bs[u2];
            }
        };
        auto DOMMA = [&](int buf) {
            int kq = lane & 3;
            unsigned ah[2][4];
            #pragma unroll
            for (int mi = 0; mi < 2; mi++) {
                int r = wm + mi * 16 + (lane >> 2);
                ah[mi][0] = sAb[buf * 1088 + kq * SA + r];
                ah[mi][1] = sAb[buf * 1088 + kq * SA + r + 8];
                ah[mi][2] = sAb[buf * 1088 + (kq + 4) * SA + r];
                ah[mi][3] = sAb[buf * 1088 + (kq + 4) * SA + r + 8];
            }
            #pragma unroll
            for (int ni = 0; ni < 4; ni++) {
                int n = wn + ni * 8 + (lane >> 2);
                unsigned b0 = sBb[buf * 1088 + kq * SA + n];
                unsigned b1 = sBb[buf * 1088 + (kq + 4) * SA + n];
                #pragma unroll
                for (int mi = 0; mi < 2; mi++)
                    MMA_FP16(acc[mi][ni], ah[mi][0], ah[mi][1], ah[mi][2], ah[mi][3], b0, b1);
            }
        };

        LOADF(0);
        STOREF(0);
        __syncthreads();
        for (int kt = 0; kt < nt; kt++) {
            if (kt + 1 < nt) LOADF(kt + 1);
            DOMMA(kt & 1);
            if (kt + 1 < nt) STOREF((kt + 1) & 1);
            __syncthreads();
        }

        #pragma unroll
        for (int mi = 0; mi < 2; mi++) {
            int r0 = row0 + wm + mi * 16 + (lane >> 2);
            int r1 = r0 + 8;
            float d0 = (r0 < NN) ? g_dinv[r0] : 0.f;
            float d1 = (r1 < NN) ? g_dinv[r1] : 0.f;
            #pragma unroll
            for (int ni = 0; ni < 4; ni++) {
                int nc = wn + ni * 8 + (lane & 3) * 2;
                if (r0 < NN)
                    *(__half2*)&g_hs[(size_t)r0 * 128 + nc] =
                        __floats2half2_rn(acc[mi][ni][0] * d0, acc[mi][ni][1] * d0);
                if (r1 < NN)
                    *(__half2*)&g_hs[(size_t)r1 * 128 + nc] =
                        __floats2half2_rn(acc[mi][ni][2] * d1, acc[mi][ni][3] * d1);
            }
        }
        __syncthreads();
    }
}

// ---------------- the fused persistent kernel --------------------------------
__global__ __launch_bounds__(256, 3) void k_fused(
    const float* __restrict__ x,
    const int* __restrict__ src, const int* __restrict__ dst,
    const int* __restrict__ batch,
    const float* __restrict__ b1, const float* __restrict__ b2, const float* __restrict__ b3,
    const float* __restrict__ g1, const float* __restrict__ be1,
    const float* __restrict__ g2, const float* __restrict__ be2,
    const float* __restrict__ g3, const float* __restrict__ be3,
    const float* __restrict__ Wf1, const float* __restrict__ bf1,
    const float* __restrict__ Wf2, const float* __restrict__ bf2,
    float* __restrict__ out) {
    extern __shared__ unsigned dsm[];
    __shared__ float shA[128], shB[128];
    __shared__ int s_lo, s_hi;

    const int nb = gridDim.x;
    const int bid = blockIdx.x;
    const int tid = threadIdx.x, lane = tid & 31, warp = tid >> 5;
    const int lane16 = lane & 15, half = lane >> 4;
    int ph = 0;

    // ===== P0: degree count =====
    for (int e = bid * 256 + tid; e < EE; e += nb * 256)
        atomicAdd(&g_deg[dst[e]], 1);
    gsync(++ph, nb);

    // ===== P1: per-block partial sums of deg =====
    const int chunk = (NN + nb - 1) / nb;
    const int start = bid * chunk;
    const int end = (start + chunk < NN) ? start + chunk : NN;
    {
        int* part = (int*)dsm;
        int s = 0;
        for (int i = start + tid; i < end; i += 256) s += __ldcg(&g_deg[i]);
        part[tid] = s;
        __syncthreads();
        for (int off = 128; off; off >>= 1) {
            if (tid < off) part[tid] += part[tid + off];
            __syncthreads();
        }
        if (tid == 0) g_bsum[bid] = part[0];
    }
    gsync(++ph, nb);

    // ===== P2: block 0 exclusive-scans block sums =====
    if (bid == 0) {
        int* part = (int*)dsm;
        int CH2 = (nb + 255) / 256;
        int s = 0;
        for (int j = 0; j < CH2; j++) {
            int idx = tid * CH2 + j;
            if (idx < nb) s += __ldcg(&g_bsum[idx]);
        }
        part[tid] = s;
        __syncthreads();
        int own = s;
        for (int off = 1; off < 256; off <<= 1) {
            int v = 0;
            if (tid >= off) v = part[tid - off];
            __syncthreads();
            if (tid >= off) part[tid] += v;
            __syncthreads();
        }
        int run = part[tid] - own;
        for (int j = 0; j < CH2; j++) {
            int idx = tid * CH2 + j;
            if (idx < nb) { g_bsum2[idx] = run; run += __ldcg(&g_bsum[idx]); }
        }
    }
    gsync(++ph, nb);

    // ===== P3: finalize rowptr/cursor/dinv, re-zero deg =====
    {
        int* part = (int*)dsm;
        int base = __ldcg(&g_bsum2[bid]);
        int CHL = (chunk + 255) / 256;
        int s = 0;
        for (int j = 0; j < CHL; j++) {
            int i = start + tid * CHL + j;
            if (i < end) s += __ldcg(&g_deg[i]);
        }
        part[tid] = s;
        __syncthreads();
        int own = s;
        for (int off = 1; off < 256; off <<= 1) {
            int v = 0;
            if (tid >= off) v = part[tid - off];
            __syncthreads();
            if (tid >= off) part[tid] += v;
            __syncthreads();
        }
        int run = base + part[tid] - own;
        for (int j = 0; j < CHL; j++) {
            int i = start + tid * CHL + j;
            if (i < end) {
                int d = __ldcg(&g_deg[i]);
                g_cursor[i] = run;
                run += d;
                g_rowptr[i + 1] = run;
                g_dinv[i] = rsqrtf((float)d + 1.0f);
                g_deg[i] = 0;
            }
        }
        if (bid == 0 && tid == 0) g_rowptr[0] = 0;
    }
    gsync(++ph, nb);

    // ===== P4 FORK: team P fills CSR || team G runs GEMM layer 1 =====
    {
        int nbP = nb / 3;
        if (nbP < 1) nbP = 1;
        if (bid < nbP) {
            for (int e = bid * 256 + tid; e < EE; e += nbP * 256) {
                int d = dst[e];
                int p = atomicAdd(&g_cursor[d], 1);
                g_col[p] = src[e];
            }
        } else {
            gemm_phase<1>(x, g_wf[0], 96, 6, bid - nbP, nb - nbP, dsm,
                          shA, shB, tid, lane, warp);
        }
    }
    gsync(++ph, nb);

    // ===== layers: (GEMM for l>=1) -> aggregate =====
    for (int l = 0; l < 3; l++) {
        if (l > 0) {
            // BN coefficients for this layer's input
            if (tid < 128) {
                float mean = __ldcg(&g_sumA[l - 1][tid]) * (1.0f / (float)NN);
                float var = __ldcg(&g_sqA[l - 1][tid]) * (1.0f / (float)NN) - mean * mean;
                const float* gm = (l == 1) ? g1 : g2;
                const float* bt = (l == 1) ? be1 : be2;
                float a = gm[tid] * rsqrtf(var + BN_EPS);
                shA[tid] = a;
                shB[tid] = bt[tid] - mean * a;
            }
            __syncthreads();
            gemm_phase<0>(x, g_wf[l], 128, 8, bid, nb, dsm, shA, shB, tid, lane, warp);
            gsync(++ph, nb);
        }

        // ---- aggregation + BN stats: 16 lanes per node, uint4 row chunks ----
        if (tid < 128) { shA[tid] = 0.f; shB[tid] = 0.f; }   // sum / sq
        __syncthreads();
        const float* bias = (l == 0) ? b1 : ((l == 1) ? b2 : b3);
        float bb[8];
        {
            float4 bl = *(const float4*)&bias[lane16 * 8];
            float4 bh = *(const float4*)&bias[lane16 * 8 + 4];
            bb[0] = bl.x; bb[1] = bl.y; bb[2] = bl.z; bb[3] = bl.w;
            bb[4] = bh.x; bb[5] = bh.y; bb[6] = bh.z; bb[7] = bh.w;
        }
        float ss[8], qq[8];
        #pragma unroll
        for (int k = 0; k < 8; k++) { ss[k] = 0.f; qq[k] = 0.f; }

        for (int grp = bid; grp < NAGG; grp += nb) {
            #pragma unroll
            for (int tt = 0; tt < 2; tt++) {
                int i = grp * 32 + warp * 4 + tt * 2 + half;
                if (i >= NN) continue;
                float a0[8], a1[8];
                #pragma unroll
                for (int k = 0; k < 8; k++) { a0[k] = 0.f; a1[k] = 0.f; }
                acc8(a0, __ldcg((const uint4*)&g_hs[(size_t)i * 128 + lane16 * 8]));  // self
                int s = g_rowptr[i], e = g_rowptr[i + 1];
                int j = s;
                for (; j + 4 <= e; j += 4) {
                    int c0 = g_col[j], c1 = g_col[j + 1], c2 = g_col[j + 2], c3 = g_col[j + 3];
                    uint4 v0 = __ldcg((const uint4*)&g_hs[(size_t)c0 * 128 + lane16 * 8]);
                    uint4 v1 = __ldcg((const uint4*)&g_hs[(size_t)c1 * 128 + lane16 * 8]);
                    uint4 v2 = __ldcg((const uint4*)&g_hs[(size_t)c2 * 128 + lane16 * 8]);
                    uint4 v3 = __ldcg((const uint4*)&g_hs[(size_t)c3 * 128 + lane16 * 8]);
                    acc8(a0, v0); acc8(a1, v1); acc8(a0, v2); acc8(a1, v3);
                }
                for (; j < e; j++) {
                    int c = g_col[j];
                    acc8(a0, __ldcg((const uint4*)&g_hs[(size_t)c * 128 + lane16 * 8]));
                }
                float di = g_dinv[i];
                float o[8];
                #pragma unroll
                for (int k = 0; k < 8; k++) {
                    o[k] = di * (a0[k] + a1[k]) + bb[k];
                    ss[k] += o[k];
                    qq[k] += o[k] * o[k];
                }
                __half2 p0 = __floats2half2_rn(o[0], o[1]);
                __half2 p1 = __floats2half2_rn(o[2], o[3]);
                __half2 p2 = __floats2half2_rn(o[4], o[5]);
                __half2 p3 = __floats2half2_rn(o[6], o[7]);
                uint4 st;
                st.x = *reinterpret_cast<unsigned*>(&p0);
                st.y = *reinterpret_cast<unsigned*>(&p1);
                st.z = *reinterpret_cast<unsigned*>(&p2);
                st.w = *reinterpret_cast<unsigned*>(&p3);
                *(uint4*)&g_agg[(size_t)i * 128 + lane16 * 8] = st;
            }
        }
        #pragma unroll
        for (int k = 0; k < 8; k++) {
            atomicAdd(&shA[lane16 * 8 + k], ss[k]);
            atomicAdd(&shB[lane16 * 8 + k], qq[k]);
        }
        __syncthreads();
        if (tid < 128) {
            atomicAdd(&g_sumA[l][tid], shA[tid]);
            atomicAdd(&g_sqA[l][tid], shB[tid]);
        }
        gsync(++ph, nb);
    }

    // ===== final: pool (BN3+ReLU) + FC head =====
    if (tid < 128) {
        float mean = __ldcg(&g_sumA[2][tid]) * (1.0f / (float)NN);
        float var = __ldcg(&g_sqA[2][tid]) * (1.0f / (float)NN) - mean * mean;
        float a = g3[tid] * rsqrtf(var + BN_EPS);
        shA[tid] = a;
        shB[tid] = be3[tid] - mean * a;
    }
    __syncthreads();
    float* red = (float*)dsm;        // 16 x 128
    float* sp = red + 2048;          // 128
    float* sz = sp + 128;            // 256
    float av[8], cv[8];
    #pragma unroll
    for (int k = 0; k < 8; k++) {
        av[k] = shA[lane16 * 8 + k];
        cv[k] = shB[lane16 * 8 + k];
    }
    for (int g = bid; g < GG; g += nb) {
        if (tid == 0) {
            int lo = 0, hi = NN;
            while (lo < hi) { int m = (lo + hi) >> 1; if (batch[m] < g) lo = m + 1; else hi = m; }
            s_lo = lo;
            lo = 0; hi = NN;
            while (lo < hi) { int m = (lo + hi) >> 1; if (batch[m] < g + 1) lo = m + 1; else hi = m; }
            s_hi = lo;
        }
        __syncthreads();
        int lo = s_lo, hi = s_hi;
        float pa[2][8];
        #pragma unroll
        for (int u = 0; u < 2; u++)
            #pragma unroll
            for (int k = 0; k < 8; k++) pa[u][k] = 0.f;
        for (int base = lo + warp * 2 + half; base < hi; base += 32) {
            #pragma unroll
            for (int u = 0; u < 2; u++) {
                int i = base + u * 16;
                if (i < hi) {
                    uint4 v = __ldcg((const uint4*)&g_agg[(size_t)i * 128 + lane16 * 8]);
                    float2 f;
                    f = __half22float2(*reinterpret_cast<__half2*>(&v.x));
                    pa[u][0] += fmaxf(fmaf(f.x, av[0], cv[0]), 0.f);
                    pa[u][1] += fmaxf(fmaf(f.y, av[1], cv[1]), 0.f);
                    f = __half22float2(*reinterpret_cast<__half2*>(&v.y));
                    pa[u][2] += fmaxf(fmaf(f.x, av[2], cv[2]), 0.f);
                    pa[u][3] += fmaxf(fmaf(f.y, av[3], cv[3]), 0.f);
                    f = __half22float2(*reinterpret_cast<__half2*>(&v.z));
                    pa[u][4] += fmaxf(fmaf(f.x, av[4], cv[4]), 0.f);
                    pa[u][5] += fmaxf(fmaf(f.y, av[5], cv[5]), 0.f);
                    f = __half22float2(*reinterpret_cast<__half2*>(&v.w));
                    pa[u][6] += fmaxf(fmaf(f.x, av[6], cv[6]), 0.f);
                    pa[u][7] += fmaxf(fmaf(f.y, av[7], cv[7]), 0.f);
                }
            }
        }
        #pragma unroll
        for (int k = 0; k < 8; k++)
            red[(warp * 2 + half) * 128 + lane16 * 8 + k] = pa[0][k] + pa[1][k];
        __syncthreads();
        if (tid < 128) {
            float s = 0.f;
            #pragma unroll
            for (int w = 0; w < 16; w++) s += red[w * 128 + tid];
            float cnt = fmaxf((float)(hi - lo), 1.0f);
            sp[tid] = s / cnt;
        }
        __syncthreads();
        float accf = bf1[tid];
        #pragma unroll 8
        for (int k = 0; k < 128; k++) accf = fmaf(sp[k], Wf1[k * 256 + tid], accf);
        sz[tid] = fmaxf(accf, 0.f);
        __syncthreads();
        if (tid < 10) {
            float o = bf2[tid];
            #pragma unroll 8
            for (int k = 0; k < 256; k++) o = fmaf(sz[k], Wf2[k * 10 + tid], o);
            out[g * 10 + tid] = o;
        }
        __syncthreads();
    }
}

// ---------------- launch ------------------------------------------------------
extern "C" void kernel_launch(void* const* d_in, const int* in_sizes, int n_in,
                              void* d_out, int out_size) {
    const float* x     = (const float*)d_in[0];
    const int*   ei    = (const int*)d_in[1];
    const int*   batch = (const int*)d_in[2];
    const float* W1 = (const float*)d_in[3];
    const float* b1 = (const float*)d_in[4];
    const float* g1 = (const float*)d_in[5];
    const float* be1 = (const float*)d_in[6];
    const float* W2 = (const float*)d_in[7];
    const float* b2 = (const float*)d_in[8];
    const float* g2 = (const float*)d_in[9];
    const float* be2 = (const float*)d_in[10];
    const float* W3 = (const float*)d_in[11];
    const float* b3 = (const float*)d_in[12];
    const float* g3 = (const float*)d_in[13];
    const float* be3 = (const float*)d_in[14];
    const float* Wf1 = (const float*)d_in[15];
    const float* bf1 = (const float*)d_in[16];
    const float* Wf2 = (const float*)d_in[17];
    const float* bf2 = (const float*)d_in[18];
    float* out = (float*)d_out;

    const int* src = ei;
    const int* dst = ei + EE;

    static int nb_cached = 0;
    if (!nb_cached) {
        int dev = 0, sms = 0, bpm = 0;
        cudaGetDevice(&dev);
        cudaDeviceGetAttribute(&sms, cudaDevAttrMultiProcessorCount, dev);
        cudaOccupancyMaxActiveBlocksPerMultiprocessor(&bpm, k_fused, 256, DSM_BYTES);
        if (bpm < 1) bpm = 1;
        long nb = (long)sms * bpm;
        if (nb > 2048) nb = 2048;
        nb_cached = (int)nb;
    }

    k_init<<<88, 256>>>(W1, W2, W3);
    k_fused<<<nb_cached, 256, DSM_BYTES>>>(
        x, src, dst, batch, b1, b2, b3,
        g1, be1, g2, be2, g3, be3,
        Wf1, bf1, Wf2, bf2, out);
}

// round 15
// speedup vs baseline: 2.2090x; 1.0489x over previous
#include <cuda_runtime.h>
#include <cuda_fp16.h>
#include <cstdint>

#define NN 50000
#define EE 800000
#define GG 64
#define BN_EPS 1e-5f
#define NTILE 782          // ceil(NN/64)
#define NAGG 1563          // ceil(NN/32)
#define SA 136             // smem stride (conflict-free)
#define DSM_BYTES 17408    // 4352 uints: 2-buf A (2176) + 2-buf B (2176)

// ---------------- device globals (no allocation) -----------------------------
__device__ __half g_hs[(size_t)NN * 128];   // GEMM out (dinv-scaled) fp16
__device__ __half g_agg[(size_t)NN * 128];  // aggregated (pre-BN) fp16
__device__ float g_dinv[NN];
__device__ int   g_deg[NN];                 // zero at load; re-zeroed each run
__device__ int   g_rowptr[NN + 1];
__device__ int   g_cursor[NN];
__device__ int   g_col[EE];
__device__ float g_sumA[3][128], g_sqA[3][128];
__device__ unsigned g_wf[3][64 * 128];      // packed half2 weights
__device__ int   g_bsum[2048], g_bsum2[2048];
__device__ unsigned g_barcnt;
__device__ volatile unsigned g_release;

// ---------------- init: reset barrier + stats, pack W ------------------------
__global__ void k_init(const float* __restrict__ W1, const float* __restrict__ W2,
                       const float* __restrict__ W3) {
    int i = blockIdx.x * blockDim.x + threadIdx.x;
    if (i == 0) { g_barcnt = 0; g_release = 0; }
    if (i < 128) {
        #pragma unroll
        for (int l = 0; l < 3; l++) { g_sumA[l][i] = 0.f; g_sqA[l][i] = 0.f; }
    }
    int l = -1, idx = 0;
    const float* W = nullptr;
    if (i < 6144) { l = 0; idx = i; W = W1; }
    else if (i < 6144 + 8192) { l = 1; idx = i - 6144; W = W2; }
    else if (i < 6144 + 16384) { l = 2; idx = i - 14336; W = W3; }
    if (l >= 0) {
        int k2 = idx >> 7, n = idx & 127;
        float w0 = W[(size_t)(2 * k2) * 128 + n];
        float w1 = W[(size_t)(2 * k2 + 1) * 128 + n];
        __half2 p = __floats2half2_rn(w0, w1);
        g_wf[l][idx] = *reinterpret_cast<unsigned*>(&p);
    }
}

// ---------------- grid barrier (all blocks resident) -------------------------
__device__ __forceinline__ void gsync(int phase, int nb) {
    __threadfence();
    __syncthreads();
    if (threadIdx.x == 0) {
        unsigned target = (unsigned)phase * (unsigned)nb;
        unsigned old = atomicAdd(&g_barcnt, 1u);
        if (old + 1u == target) {
            g_release = (unsigned)phase;
            __threadfence();
        } else {
            while (g_release < (unsigned)phase) __nanosleep(64);
            __threadfence();
        }
    }
    __syncthreads();
}

#define MMA_FP16(C, a0, a1, a2, a3, b0, b1)                                        \
    asm volatile(                                                                  \
        "mma.sync.aligned.m16n8k16.row.col.f32.f16.f16.f32 "                       \
        "{%0,%1,%2,%3},{%4,%5,%6,%7},{%8,%9},{%0,%1,%2,%3};"                       \
        : "+f"((C)[0]), "+f"((C)[1]), "+f"((C)[2]), "+f"((C)[3])                   \
        : "r"(a0), "r"(a1), "r"(a2), "r"(a3), "r"(b0), "r"(b1))

// unpack uint4 (8 halfs) and add into 8 fp32 accumulators
__device__ __forceinline__ void acc8(float* a, uint4 u) {
    float2 f;
    f = __half22float2(*reinterpret_cast<__half2*>(&u.x)); a[0] += f.x; a[1] += f.y;
    f = __half22float2(*reinterpret_cast<__half2*>(&u.y)); a[2] += f.x; a[3] += f.y;
    f = __half22float2(*reinterpret_cast<__half2*>(&u.z)); a[4] += f.x; a[5] += f.y;
    f = __half22float2(*reinterpret_cast<__half2*>(&u.w)); a[6] += f.x; a[7] += f.y;
}

// ---------------- GEMM tile phase (shared by fork & layer loop) --------------
// L0=1: A = x (fp32, no BN). L0=0: A = g_agg (fp16, BN+ReLU via shA/shB).
template <int L0>
__device__ __forceinline__ void gemm_phase(
    const float* __restrict__ x, const unsigned* __restrict__ Wf,
    int K, int nt, int tstart, int tstride, unsigned* dsm,
    const float* shA, const float* shB, int tid, int lane, int warp) {
    unsigned* sAb = dsm;          // 2 x 1088
    unsigned* sBb = dsm + 2176;   // 2 x 1088
    int wm = (warp >> 2) * 32;
    int wn = (warp & 3) * 32;
    for (int t = tstart; t < NTILE; t += tstride) {
        int row0 = t * 64;
        float acc[2][4][4];
        #pragma unroll
        for (int mi = 0; mi < 2; mi++)
            #pragma unroll
            for (int ni = 0; ni < 4; ni++)
                #pragma unroll
                for (int q = 0; q < 4; q++) acc[mi][ni][q] = 0.f;

        float ae[4];
        unsigned bs[4];

        auto LOADF = [&](int kt) {
            int k0 = kt * 16;
            int m = tid >> 2, kv = (tid & 3) * 4, gm = row0 + m;
            if (L0) {
                float4 v = make_float4(0.f, 0.f, 0.f, 0.f);
                if (gm < NN) v = *(const float4*)&x[(size_t)gm * 96 + k0 + kv];
                ae[0] = v.x; ae[1] = v.y; ae[2] = v.z; ae[3] = v.w;
            } else {
                uint2 hv = make_uint2(0u, 0u);
                if (gm < NN) hv = __ldcg((const uint2*)&g_agg[(size_t)gm * 128 + k0 + kv]);
                float2 f0 = __half22float2(*reinterpret_cast<__half2*>(&hv.x));
                float2 f1 = __half22float2(*reinterpret_cast<__half2*>(&hv.y));
                int kb = k0 + kv;
                ae[0] = fmaxf(fmaf(f0.x, shA[kb + 0], shB[kb + 0]), 0.f);
                ae[1] = fmaxf(fmaf(f0.y, shA[kb + 1], shB[kb + 1]), 0.f);
                ae[2] = fmaxf(fmaf(f1.x, shA[kb + 2], shB[kb + 2]), 0.f);
                ae[3] = fmaxf(fmaf(f1.y, shA[kb + 3], shB[kb + 3]), 0.f);
            }
            int k2b = kt * 8;
            #pragma unroll
            for (int u2 = 0; u2 < 4; u2++) {
                int u = tid + u2 * 256;
                int k2 = u >> 7, n = u & 127;
                bs[u2] = Wf[(k2b + k2) * 128 + n];
            }
        };
        auto STOREF = [&](int buf) {
            int m = tid >> 2, kv = (tid & 3) * 4, k2 = kv >> 1;
            __half2 p0 = __floats2half2_rn(ae[0], ae[1]);
            __half2 p1 = __floats2half2_rn(ae[2], ae[3]);
            sAb[buf * 1088 + k2 * SA + m] = *reinterpret_cast<unsigned*>(&p0);
            sAb[buf * 1088 + (k2 + 1) * SA + m] = *reinterpret_cast<unsigned*>(&p1);
            #pragma unroll
            for (int u2 = 0; u2 < 4; u2++) {
                int u = tid + u2 * 256;
                int k2u = u >> 7, n = u & 127;
                sBb[buf * 1088 + k2u * SA + n] = bs[u2];
            }
        };
        auto DOMMA = [&](int buf) {
            int kq = lane & 3;
            unsigned ah[2][4];
            #pragma unroll
            for (int mi = 0; mi < 2; mi++) {
                int r = wm + mi * 16 + (lane >> 2);
                ah[mi][0] = sAb[buf * 1088 + kq * SA + r];
                ah[mi][1] = sAb[buf * 1088 + kq * SA + r + 8];
                ah[mi][2] = sAb[buf * 1088 + (kq + 4) * SA + r];
                ah[mi][3] = sAb[buf * 1088 + (kq + 4) * SA + r + 8];
            }
            #pragma unroll
            for (int ni = 0; ni < 4; ni++) {
                int n = wn + ni * 8 + (lane >> 2);
                unsigned b0 = sBb[buf * 1088 + kq * SA + n];
                unsigned b1 = sBb[buf * 1088 + (kq + 4) * SA + n];
                #pragma unroll
                for (int mi = 0; mi < 2; mi++)
                    MMA_FP16(acc[mi][ni], ah[mi][0], ah[mi][1], ah[mi][2], ah[mi][3], b0, b1);
            }
        };

        LOADF(0);
        STOREF(0);
        __syncthreads();
        for (int kt = 0; kt < nt; kt++) {
            if (kt + 1 < nt) LOADF(kt + 1);
            DOMMA(kt & 1);
            if (kt + 1 < nt) STOREF((kt + 1) & 1);
            __syncthreads();
        }

        #pragma unroll
        for (int mi = 0; mi < 2; mi++) {
            int r0 = row0 + wm + mi * 16 + (lane >> 2);
            int r1 = r0 + 8;
            float d0 = (r0 < NN) ? g_dinv[r0] : 0.f;
            float d1 = (r1 < NN) ? g_dinv[r1] : 0.f;
            #pragma unroll
            for (int ni = 0; ni < 4; ni++) {
                int nc = wn + ni * 8 + (lane & 3) * 2;
                if (r0 < NN)
                    *(__half2*)&g_hs[(size_t)r0 * 128 + nc] =
                        __floats2half2_rn(acc[mi][ni][0] * d0, acc[mi][ni][1] * d0);
                if (r1 < NN)
                    *(__half2*)&g_hs[(size_t)r1 * 128 + nc] =
                        __floats2half2_rn(acc[mi][ni][2] * d1, acc[mi][ni][3] * d1);
            }
        }
        __syncthreads();
    }
}

// ---------------- the fused persistent kernel --------------------------------
__global__ __launch_bounds__(256, 3) void k_fused(
    const float* __restrict__ x,
    const int* __restrict__ src, const int* __restrict__ dst,
    const int* __restrict__ batch,
    const float* __restrict__ b1, const float* __restrict__ b2, const float* __restrict__ b3,
    const float* __restrict__ g1, const float* __restrict__ be1,
    const float* __restrict__ g2, const float* __restrict__ be2,
    const float* __restrict__ g3, const float* __restrict__ be3,
    const float* __restrict__ Wf1, const float* __restrict__ bf1,
    const float* __restrict__ Wf2, const float* __restrict__ bf2,
    float* __restrict__ out) {
    extern __shared__ unsigned dsm[];
    __shared__ float shA[128], shB[128];
    __shared__ int s_lo, s_hi;

    const int nb = gridDim.x;
    const int bid = blockIdx.x;
    const int tid = threadIdx.x, lane = tid & 31, warp = tid >> 5;
    const int lane16 = lane & 15, half = lane >> 4;
    int ph = 0;

    // ===== P0: degree count =====
    for (int e = bid * 256 + tid; e < EE; e += nb * 256)
        atomicAdd(&g_deg[dst[e]], 1);
    gsync(++ph, nb);

    // ===== P1: per-block partial sums of deg =====
    const int chunk = (NN + nb - 1) / nb;
    const int start = bid * chunk;
    const int end = (start + chunk < NN) ? start + chunk : NN;
    {
        int* part = (int*)dsm;
        int s = 0;
        for (int i = start + tid; i < end; i += 256) s += __ldcg(&g_deg[i]);
        part[tid] = s;
        __syncthreads();
        for (int off = 128; off; off >>= 1) {
            if (tid < off) part[tid] += part[tid + off];
            __syncthreads();
        }
        if (tid == 0) g_bsum[bid] = part[0];
    }
    gsync(++ph, nb);

    // ===== P2: block 0 exclusive-scans block sums =====
    if (bid == 0) {
        int* part = (int*)dsm;
        int CH2 = (nb + 255) / 256;
        int s = 0;
        for (int j = 0; j < CH2; j++) {
            int idx = tid * CH2 + j;
            if (idx < nb) s += __ldcg(&g_bsum[idx]);
        }
        part[tid] = s;
        __syncthreads();
        int own = s;
        for (int off = 1; off < 256; off <<= 1) {
            int v = 0;
            if (tid >= off) v = part[tid - off];
            __syncthreads();
            if (tid >= off) part[tid] += v;
            __syncthreads();
        }
        int run = part[tid] - own;
        for (int j = 0; j < CH2; j++) {
            int idx = tid * CH2 + j;
            if (idx < nb) { g_bsum2[idx] = run; run += __ldcg(&g_bsum[idx]); }
        }
    }
    gsync(++ph, nb);

    // ===== P3: finalize rowptr/cursor/dinv, re-zero deg =====
    {
        int* part = (int*)dsm;
        int base = __ldcg(&g_bsum2[bid]);
        int CHL = (chunk + 255) / 256;
        int s = 0;
        for (int j = 0; j < CHL; j++) {
            int i = start + tid * CHL + j;
            if (i < end) s += __ldcg(&g_deg[i]);
        }
        part[tid] = s;
        __syncthreads();
        int own = s;
        for (int off = 1; off < 256; off <<= 1) {
            int v = 0;
            if (tid >= off) v = part[tid - off];
            __syncthreads();
            if (tid >= off) part[tid] += v;
            __syncthreads();
        }
        int run = base + part[tid] - own;
        for (int j = 0; j < CHL; j++) {
            int i = start + tid * CHL + j;
            if (i < end) {
                int d = __ldcg(&g_deg[i]);
                g_cursor[i] = run;
                run += d;
                g_rowptr[i + 1] = run;
                g_dinv[i] = rsqrtf((float)d + 1.0f);
                g_deg[i] = 0;
            }
        }
        if (bid == 0 && tid == 0) g_rowptr[0] = 0;
    }
    gsync(++ph, nb);

    // ===== P4 FORK: team P (5/9) fills CSR || team G (4/9) runs GEMM layer 1 =====
    {
        int nbP = (nb * 5) / 9;
        if (nbP < 1) nbP = 1;
        if (bid < nbP) {
            for (int e = bid * 256 + tid; e < EE; e += nbP * 256) {
                int d = dst[e];
                int p = atomicAdd(&g_cursor[d], 1);
                g_col[p] = src[e];
            }
        } else {
            gemm_phase<1>(x, g_wf[0], 96, 6, bid - nbP, nb - nbP, dsm,
                          shA, shB, tid, lane, warp);
        }
    }
    gsync(++ph, nb);

    // ===== layers: (GEMM for l>=1) -> aggregate =====
    for (int l = 0; l < 3; l++) {
        if (l > 0) {
            // BN coefficients for this layer's input
            if (tid < 128) {
                float mean = __ldcg(&g_sumA[l - 1][tid]) * (1.0f / (float)NN);
                float var = __ldcg(&g_sqA[l - 1][tid]) * (1.0f / (float)NN) - mean * mean;
                const float* gm = (l == 1) ? g1 : g2;
                const float* bt = (l == 1) ? be1 : be2;
                float a = gm[tid] * rsqrtf(var + BN_EPS);
                shA[tid] = a;
                shB[tid] = bt[tid] - mean * a;
            }
            __syncthreads();
            gemm_phase<0>(x, g_wf[l], 128, 8, bid, nb, dsm, shA, shB, tid, lane, warp);
            gsync(++ph, nb);
        }

        // ---- aggregation + BN stats: 16 lanes per node, uint4 chunks, MLP-8 ----
        if (tid < 128) { shA[tid] = 0.f; shB[tid] = 0.f; }   // sum / sq
        __syncthreads();
        const float* bias = (l == 0) ? b1 : ((l == 1) ? b2 : b3);
        float bb[8];
        {
            float4 bl = *(const float4*)&bias[lane16 * 8];
            float4 bh = *(const float4*)&bias[lane16 * 8 + 4];
            bb[0] = bl.x; bb[1] = bl.y; bb[2] = bl.z; bb[3] = bl.w;
            bb[4] = bh.x; bb[5] = bh.y; bb[6] = bh.z; bb[7] = bh.w;
        }
        float ss[8], qq[8];
        #pragma unroll
        for (int k = 0; k < 8; k++) { ss[k] = 0.f; qq[k] = 0.f; }

        for (int grp = bid; grp < NAGG; grp += nb) {
            #pragma unroll
            for (int tt = 0; tt < 2; tt++) {
                int i = grp * 32 + warp * 4 + tt * 2 + half;
                if (i >= NN) continue;
                float a0[8], a1[8];
                #pragma unroll
                for (int k = 0; k < 8; k++) { a0[k] = 0.f; a1[k] = 0.f; }
                acc8(a0, __ldcg((const uint4*)&g_hs[(size_t)i * 128 + lane16 * 8]));  // self
                int s = g_rowptr[i], e = g_rowptr[i + 1];
                int j = s;
                for (; j + 8 <= e; j += 8) {
                    int c0 = g_col[j],     c1 = g_col[j + 1], c2 = g_col[j + 2], c3 = g_col[j + 3];
                    int c4 = g_col[j + 4], c5 = g_col[j + 5], c6 = g_col[j + 6], c7 = g_col[j + 7];
                    uint4 v0 = __ldcg((const uint4*)&g_hs[(size_t)c0 * 128 + lane16 * 8]);
                    uint4 v1 = __ldcg((const uint4*)&g_hs[(size_t)c1 * 128 + lane16 * 8]);
                    uint4 v2 = __ldcg((const uint4*)&g_hs[(size_t)c2 * 128 + lane16 * 8]);
                    uint4 v3 = __ldcg((const uint4*)&g_hs[(size_t)c3 * 128 + lane16 * 8]);
                    uint4 v4 = __ldcg((const uint4*)&g_hs[(size_t)c4 * 128 + lane16 * 8]);
                    uint4 v5 = __ldcg((const uint4*)&g_hs[(size_t)c5 * 128 + lane16 * 8]);
                    uint4 v6 = __ldcg((const uint4*)&g_hs[(size_t)c6 * 128 + lane16 * 8]);
                    uint4 v7 = __ldcg((const uint4*)&g_hs[(size_t)c7 * 128 + lane16 * 8]);
                    acc8(a0, v0); acc8(a1, v1); acc8(a0, v2); acc8(a1, v3);
                    acc8(a0, v4); acc8(a1, v5); acc8(a0, v6); acc8(a1, v7);
                }
                for (; j + 4 <= e; j += 4) {
                    int c0 = g_col[j], c1 = g_col[j + 1], c2 = g_col[j + 2], c3 = g_col[j + 3];
                    uint4 v0 = __ldcg((const uint4*)&g_hs[(size_t)c0 * 128 + lane16 * 8]);
                    uint4 v1 = __ldcg((const uint4*)&g_hs[(size_t)c1 * 128 + lane16 * 8]);
                    uint4 v2 = __ldcg((const uint4*)&g_hs[(size_t)c2 * 128 + lane16 * 8]);
                    uint4 v3 = __ldcg((const uint4*)&g_hs[(size_t)c3 * 128 + lane16 * 8]);
                    acc8(a0, v0); acc8(a1, v1); acc8(a0, v2); acc8(a1, v3);
                }
                for (; j < e; j++) {
                    int c = g_col[j];
                    acc8(a0, __ldcg((const uint4*)&g_hs[(size_t)c * 128 + lane16 * 8]));
                }
                float di = g_dinv[i];
                float o[8];
                #pragma unroll
                for (int k = 0; k < 8; k++) {
                    o[k] = di * (a0[k] + a1[k]) + bb[k];
                    ss[k] += o[k];
                    qq[k] += o[k] * o[k];
                }
                __half2 p0 = __floats2half2_rn(o[0], o[1]);
                __half2 p1 = __floats2half2_rn(o[2], o[3]);
                __half2 p2 = __floats2half2_rn(o[4], o[5]);
                __half2 p3 = __floats2half2_rn(o[6], o[7]);
                uint4 st;
                st.x = *reinterpret_cast<unsigned*>(&p0);
                st.y = *reinterpret_cast<unsigned*>(&p1);
                st.z = *reinterpret_cast<unsigned*>(&p2);
                st.w = *reinterpret_cast<unsigned*>(&p3);
                *(uint4*)&g_agg[(size_t)i * 128 + lane16 * 8] = st;
            }
        }
        #pragma unroll
        for (int k = 0; k < 8; k++) {
            atomicAdd(&shA[lane16 * 8 + k], ss[k]);
            atomicAdd(&shB[lane16 * 8 + k], qq[k]);
        }
        __syncthreads();
        if (tid < 128) {
            atomicAdd(&g_sumA[l][tid], shA[tid]);
            atomicAdd(&g_sqA[l][tid], shB[tid]);
        }
        gsync(++ph, nb);
    }

    // ===== final: pool (BN3+ReLU) + FC head =====
    if (tid < 128) {
        float mean = __ldcg(&g_sumA[2][tid]) * (1.0f / (float)NN);
        float var = __ldcg(&g_sqA[2][tid]) * (1.0f / (float)NN) - mean * mean;
        float a = g3[tid] * rsqrtf(var + BN_EPS);
        shA[tid] = a;
        shB[tid] = be3[tid] - mean * a;
    }
    __syncthreads();
    float* red = (float*)dsm;        // 16 x 128
    float* sp = red + 2048;          // 128
    float* sz = sp + 128;            // 256
    float av[8], cv[8];
    #pragma unroll
    for (int k = 0; k < 8; k++) {
        av[k] = shA[lane16 * 8 + k];
        cv[k] = shB[lane16 * 8 + k];
    }
    for (int g = bid; g < GG; g += nb) {
        if (tid == 0) {
            int lo = 0, hi = NN;
            while (lo < hi) { int m = (lo + hi) >> 1; if (batch[m] < g) lo = m + 1; else hi = m; }
            s_lo = lo;
            lo = 0; hi = NN;
            while (lo < hi) { int m = (lo + hi) >> 1; if (batch[m] < g + 1) lo = m + 1; else hi = m; }
            s_hi = lo;
        }
        __syncthreads();
        int lo = s_lo, hi = s_hi;
        float pa[2][8];
        #pragma unroll
        for (int u = 0; u < 2; u++)
            #pragma unroll
            for (int k = 0; k < 8; k++) pa[u][k] = 0.f;
        for (int base = lo + warp * 2 + half; base < hi; base += 32) {
            #pragma unroll
            for (int u = 0; u < 2; u++) {
                int i = base + u * 16;
                if (i < hi) {
                    uint4 v = __ldcg((const uint4*)&g_agg[(size_t)i * 128 + lane16 * 8]);
                    float2 f;
                    f = __half22float2(*reinterpret_cast<__half2*>(&v.x));
                    pa[u][0] += fmaxf(fmaf(f.x, av[0], cv[0]), 0.f);
                    pa[u][1] += fmaxf(fmaf(f.y, av[1], cv[1]), 0.f);
                    f = __half22float2(*reinterpret_cast<__half2*>(&v.y));
                    pa[u][2] += fmaxf(fmaf(f.x, av[2], cv[2]), 0.f);
                    pa[u][3] += fmaxf(fmaf(f.y, av[3], cv[3]), 0.f);
                    f = __half22float2(*reinterpret_cast<__half2*>(&v.z));
                    pa[u][4] += fmaxf(fmaf(f.x, av[4], cv[4]), 0.f);
                    pa[u][5] += fmaxf(fmaf(f.y, av[5], cv[5]), 0.f);
                    f = __half22float2(*reinterpret_cast<__half2*>(&v.w));
                    pa[u][6] += fmaxf(fmaf(f.x, av[6], cv[6]), 0.f);
                    pa[u][7] += fmaxf(fmaf(f.y, av[7], cv[7]), 0.f);
                }
            }
        }
        #pragma unroll
        for (int k = 0; k < 8; k++)
            red[(warp * 2 + half) * 128 + lane16 * 8 + k] = pa[0][k] + pa[1][k];
        __syncthreads();
        if (tid < 128) {
            float s = 0.f;
            #pragma unroll
            for (int w = 0; w < 16; w++) s += red[w * 128 + tid];
            float cnt = fmaxf((float)(hi - lo), 1.0f);
            sp[tid] = s / cnt;
        }
        __syncthreads();
        float accf = bf1[tid];
        #pragma unroll 8
        for (int k = 0; k < 128; k++) accf = fmaf(sp[k], Wf1[k * 256 + tid], accf);
        sz[tid] = fmaxf(accf, 0.f);
        __syncthreads();
        if (tid < 10) {
            float o = bf2[tid];
            #pragma unroll 8
            for (int k = 0; k < 256; k++) o = fmaf(sz[k], Wf2[k * 10 + tid], o);
            out[g * 10 + tid] = o;
        }
        __syncthreads();
    }
}

// ---------------- launch ------------------------------------------------------
extern "C" void kernel_launch(void* const* d_in, const int* in_sizes, int n_in,
                              void* d_out, int out_size) {
    const float* x     = (const float*)d_in[0];
    const int*   ei    = (const int*)d_in[1];
    const int*   batch = (const int*)d_in[2];
    const float* W1 = (const float*)d_in[3];
    const float* b1 = (const float*)d_in[4];
    const float* g1 = (const float*)d_in[5];
    const float* be1 = (const float*)d_in[6];
    const float* W2 = (const float*)d_in[7];
    const float* b2 = (const float*)d_in[8];
    const float* g2 = (const float*)d_in[9];
    const float* be2 = (const float*)d_in[10];
    const float* W3 = (const float*)d_in[11];
    const float* b3 = (const float*)d_in[12];
    const float* g3 = (const float*)d_in[13];
    const float* be3 = (const float*)d_in[14];
    const float* Wf1 = (const float*)d_in[15];
    const float* bf1 = (const float*)d_in[16];
    const float* Wf2 = (const float*)d_in[17];
    const float* bf2 = (const float*)d_in[18];
    float* out = (float*)d_out;

    const int* src = ei;
    const int* dst = ei + EE;

    static int nb_cached = 0;
    if (!nb_cached) {
        int dev = 0, sms = 0, bpm = 0;
        cudaGetDevice(&dev);
        cudaDeviceGetAttribute(&sms, cudaDevAttrMultiProcessorCount, dev);
        cudaOccupancyMaxActiveBlocksPerMultiprocessor(&bpm, k_fused, 256, DSM_BYTES);
        if (bpm < 1) bpm = 1;
        long nb = (long)sms * bpm;
        if (nb > 2048) nb = 2048;
        nb_cached = (int)nb;
    }

    k_init<<<88, 256>>>(W1, W2, W3);
    k_fused<<<nb_cached, 256, DSM_BYTES>>>(
        x, src, dst, batch, b1, b2, b3,
        g1, be1, g2, be2, g3, be3,
        Wf1, bf1, Wf2, bf2, out);
}